// round 3
// baseline (speedup 1.0000x reference)
#include <cuda_runtime.h>
#include <math.h>

#define N_NODES 100000
#define N_EDGES 3200000
#define NFEAT   512
#define HIDDEN  256
#define NCLASS  64
#define KITER   10

// ---------------- device scratch (no allocations allowed) ----------------
__device__ int    g_is64;
__device__ int    g_ecnt[N_NODES];
__device__ int    g_pos[N_NODES];
__device__ int    g_off[N_NODES + 1];
__device__ float  g_dinv[N_NODES];
__device__ int    g_rowi[N_EDGES];
__device__ int    g_coli[N_EDGES];
__device__ float2 g_edge[N_EDGES];                       // (src as int bits, norm)
__device__ float  g_mid[(size_t)N_NODES * HIDDEN];       // relu(x@W1+b1)
__device__ float  g_h0[(size_t)N_NODES * NCLASS];
__device__ float  g_h1[(size_t)N_NODES * NCLASS];
__device__ float  g_hidden[(size_t)N_NODES * NCLASS];

// ---------------- dtype detection: int64 vs int32 edge_index ----------------
// If int64 (values < 2^31), odd 32-bit words are all zero. If int32, odd words
// are random node indices -> essentially never all zero across 64 samples.
__global__ void k_detect(const int* __restrict__ ei32) {
    if (threadIdx.x == 0 && blockIdx.x == 0) {
        int allzero = 1;
        for (int i = 0; i < 64; i++)
            if (ei32[2 * i + 1] != 0) { allzero = 0; break; }
        g_is64 = allzero;
    }
}

// ---------------- preprocessing ----------------
__global__ void k_init() {
    int i = blockIdx.x * blockDim.x + threadIdx.x;
    if (i < N_NODES) { g_ecnt[i] = 0; g_pos[i] = 0; }
}

__global__ void k_convert(const void* __restrict__ ei) {
    int e = blockIdx.x * blockDim.x + threadIdx.x;
    if (e >= N_EDGES) return;
    int r, c;
    if (g_is64) {
        const long long* p = (const long long*)ei;
        r = (int)p[e];
        c = (int)p[(size_t)N_EDGES + e];
    } else {
        const int* p = (const int*)ei;
        r = p[e];
        c = p[(size_t)N_EDGES + e];
    }
    if ((unsigned)r >= N_NODES || (unsigned)c >= N_NODES) { g_rowi[e] = -1; g_coli[e] = -1; return; }
    g_rowi[e] = r;
    g_coli[e] = c;
    atomicAdd(&g_ecnt[c], 1);
}

__global__ void k_dinv() {
    int i = blockIdx.x * blockDim.x + threadIdx.x;
    if (i < N_NODES) g_dinv[i] = rsqrtf((float)(g_ecnt[i] + 1));  // +1 self loop
}

// single-block exclusive scan of g_ecnt -> g_off (1024 threads)
__global__ void k_scan() {
    __shared__ int warp_sums[32];
    __shared__ int carry_s;
    const int n = N_NODES;
    int tid = threadIdx.x, lane = tid & 31, wid = tid >> 5;
    if (tid == 0) carry_s = 0;
    __syncthreads();
    for (int base = 0; base < n; base += 1024) {
        int i = base + tid;
        int v = (i < n) ? g_ecnt[i] : 0;
        int x = v;
        #pragma unroll
        for (int o = 1; o < 32; o <<= 1) {
            int t = __shfl_up_sync(0xFFFFFFFFu, x, o);
            if (lane >= o) x += t;
        }
        if (lane == 31) warp_sums[wid] = x;
        __syncthreads();
        if (wid == 0) {
            int ws = warp_sums[lane];
            int y = ws;
            #pragma unroll
            for (int o = 1; o < 32; o <<= 1) {
                int t = __shfl_up_sync(0xFFFFFFFFu, y, o);
                if (lane >= o) y += t;
            }
            warp_sums[lane] = y - ws;  // exclusive warp offsets
        }
        __syncthreads();
        int excl = carry_s + warp_sums[wid] + x - v;
        if (i < n) g_off[i] = excl;
        __syncthreads();
        if (tid == 1023) carry_s = excl + v;
        __syncthreads();
    }
    if (threadIdx.x == 0) g_off[n] = carry_s;
}

__global__ void k_scatter() {
    int e = blockIdx.x * blockDim.x + threadIdx.x;
    if (e >= N_EDGES) return;
    int r = g_rowi[e], c = g_coli[e];
    if (r < 0 || c < 0) return;
    int p = g_off[c] + atomicAdd(&g_pos[c], 1);
    if (p >= N_EDGES) return;  // defensive; never taken with clean data
    float w = g_dinv[r] * g_dinv[c];
    g_edge[p] = make_float2(__int_as_float(r), w);
}

// ---------------- GEMM1: g_mid = relu(x @ W1 + b1) ----------------
// x:[M,512]  W1:[512,256]  tiles 128x128x8, 256 thr, 8x8/thread
__global__ __launch_bounds__(256) void k_gemm1(const float* __restrict__ A,
                                               const float* __restrict__ W,
                                               const float* __restrict__ bias) {
    const int K = NFEAT, N = HIDDEN;
    __shared__ float As[8][128];
    __shared__ float Bs[8][128];
    int tid = threadIdx.x;
    int rowbase = blockIdx.y * 128;
    int colbase = blockIdx.x * 128;
    int arow = tid >> 1, acol = (tid & 1) * 4;
    int brow = tid >> 5, bcol = (tid & 31) * 4;
    int tx = tid & 15, ty = tid >> 4;
    float acc[8][8] = {};
    bool aok = (rowbase + arow) < N_NODES;
    const float* Ap = A + (size_t)(rowbase + arow) * K + acol;
    for (int k0 = 0; k0 < K; k0 += 8) {
        float4 av = aok ? *(const float4*)(Ap + k0) : make_float4(0.f, 0.f, 0.f, 0.f);
        As[acol + 0][arow] = av.x;
        As[acol + 1][arow] = av.y;
        As[acol + 2][arow] = av.z;
        As[acol + 3][arow] = av.w;
        *(float4*)&Bs[brow][bcol] = *(const float4*)&W[(size_t)(k0 + brow) * N + colbase + bcol];
        __syncthreads();
        #pragma unroll
        for (int kk = 0; kk < 8; kk++) {
            float a[8], b[8];
            *(float4*)(a)     = *(float4*)&As[kk][ty * 8];
            *(float4*)(a + 4) = *(float4*)&As[kk][ty * 8 + 4];
            *(float4*)(b)     = *(float4*)&Bs[kk][tx * 8];
            *(float4*)(b + 4) = *(float4*)&Bs[kk][tx * 8 + 4];
            #pragma unroll
            for (int i = 0; i < 8; i++)
                #pragma unroll
                for (int j = 0; j < 8; j++)
                    acc[i][j] = fmaf(a[i], b[j], acc[i][j]);
        }
        __syncthreads();
    }
    #pragma unroll
    for (int i = 0; i < 8; i++) {
        int r = rowbase + ty * 8 + i;
        if (r < N_NODES) {
            #pragma unroll
            for (int j = 0; j < 8; j += 4) {
                int c = colbase + tx * 8 + j;
                float4 o;
                o.x = fmaxf(acc[i][j + 0] + bias[c + 0], 0.f);
                o.y = fmaxf(acc[i][j + 1] + bias[c + 1], 0.f);
                o.z = fmaxf(acc[i][j + 2] + bias[c + 2], 0.f);
                o.w = fmaxf(acc[i][j + 3] + bias[c + 3], 0.f);
                *(float4*)&g_mid[(size_t)r * HIDDEN + c] = o;
            }
        }
    }
}

// ---------------- GEMM2: g_h0 = g_mid @ W2 + b2 ; g_hidden = temp[0]*g_h0 ----
// tiles 128x64x8, 256 thr, 8x4/thread
__global__ __launch_bounds__(256) void k_gemm2(const float* __restrict__ W,
                                               const float* __restrict__ bias,
                                               const float* __restrict__ temp) {
    const int K = HIDDEN, N = NCLASS;
    __shared__ float As[8][128];
    __shared__ float Bs[8][64];
    int tid = threadIdx.x;
    int rowbase = blockIdx.x * 128;
    int arow = tid >> 1, acol = (tid & 1) * 4;
    int tx = tid & 15, ty = tid >> 4;
    float acc[8][4] = {};
    bool aok = (rowbase + arow) < N_NODES;
    const float* Ap = g_mid + (size_t)(rowbase + arow) * K + acol;
    for (int k0 = 0; k0 < K; k0 += 8) {
        float4 av = aok ? *(const float4*)(Ap + k0) : make_float4(0.f, 0.f, 0.f, 0.f);
        As[acol + 0][arow] = av.x;
        As[acol + 1][arow] = av.y;
        As[acol + 2][arow] = av.z;
        As[acol + 3][arow] = av.w;
        if (tid < 128) {
            int brow = tid >> 4, bcol = (tid & 15) * 4;
            *(float4*)&Bs[brow][bcol] = *(const float4*)&W[(size_t)(k0 + brow) * N + bcol];
        }
        __syncthreads();
        #pragma unroll
        for (int kk = 0; kk < 8; kk++) {
            float a[8], b[4];
            *(float4*)(a)     = *(float4*)&As[kk][ty * 8];
            *(float4*)(a + 4) = *(float4*)&As[kk][ty * 8 + 4];
            *(float4*)(b)     = *(float4*)&Bs[kk][tx * 4];
            #pragma unroll
            for (int i = 0; i < 8; i++)
                #pragma unroll
                for (int j = 0; j < 4; j++)
                    acc[i][j] = fmaf(a[i], b[j], acc[i][j]);
        }
        __syncthreads();
    }
    float t0 = temp[0];
    #pragma unroll
    for (int i = 0; i < 8; i++) {
        int r = rowbase + ty * 8 + i;
        if (r < N_NODES) {
            int c = tx * 4;
            float4 o;
            o.x = acc[i][0] + bias[c + 0];
            o.y = acc[i][1] + bias[c + 1];
            o.z = acc[i][2] + bias[c + 2];
            o.w = acc[i][3] + bias[c + 3];
            *(float4*)&g_h0[(size_t)r * N + c] = o;
            float4 hh;
            hh.x = t0 * o.x; hh.y = t0 * o.y; hh.z = t0 * o.z; hh.w = t0 * o.w;
            *(float4*)&g_hidden[(size_t)r * N + c] = hh;
        }
    }
}

// ---------------- propagation: hout = Ahat @ hin ; hidden += temp[kidx]*hout --
// one warp per node, float2 per lane (64 floats/row)
__global__ __launch_bounds__(256) void k_prop(int parity,
                                              const float* __restrict__ temp,
                                              int kidx) {
    int t = blockIdx.x * blockDim.x + threadIdx.x;
    int c = t >> 5, lane = t & 31;
    if (c >= N_NODES) return;
    const float* hin = parity ? g_h1 : g_h0;
    float*       hout = parity ? g_h0 : g_h1;
    const float2* hin2 = (const float2*)hin;

    float dc = g_dinv[c];
    float sw = dc * dc;  // self-loop weight
    float2 v = hin2[(size_t)c * 32 + lane];
    float2 acc;
    acc.x = sw * v.x;
    acc.y = sw * v.y;

    int b = g_off[c], e = g_off[c + 1];
    for (int p = b; p < e; p++) {
        float2 ed = __ldg(&g_edge[p]);           // uniform per warp (broadcast)
        int s = __float_as_int(ed.x);
        float w = ed.y;
        float2 hv = hin2[(size_t)s * 32 + lane]; // L2-resident gather
        acc.x = fmaf(w, hv.x, acc.x);
        acc.y = fmaf(w, hv.y, acc.y);
    }
    ((float2*)hout)[(size_t)c * 32 + lane] = acc;

    float tk = temp[kidx];
    float2* hid2 = (float2*)g_hidden;
    float2 h = hid2[(size_t)c * 32 + lane];
    h.x = fmaf(tk, acc.x, h.x);
    h.y = fmaf(tk, acc.y, h.y);
    hid2[(size_t)c * 32 + lane] = h;
}

// ---------------- log_softmax over 64 classes: one warp per row --------------
__global__ __launch_bounds__(256) void k_softmax(float* __restrict__ out) {
    int t = blockIdx.x * blockDim.x + threadIdx.x;
    int r = t >> 5, lane = t & 31;
    if (r >= N_NODES) return;
    const float2* h2 = (const float2*)g_hidden;
    float2 v = h2[(size_t)r * 32 + lane];
    float m = fmaxf(v.x, v.y);
    #pragma unroll
    for (int o = 16; o > 0; o >>= 1) m = fmaxf(m, __shfl_xor_sync(0xFFFFFFFFu, m, o));
    float s = expf(v.x - m) + expf(v.y - m);
    #pragma unroll
    for (int o = 16; o > 0; o >>= 1) s += __shfl_xor_sync(0xFFFFFFFFu, s, o);
    float ls = m + logf(s);
    float2 o2;
    o2.x = v.x - ls;
    o2.y = v.y - ls;
    ((float2*)out)[(size_t)r * 32 + lane] = o2;
}

// ---------------- driver ----------------
extern "C" void kernel_launch(void* const* d_in, const int* in_sizes, int n_in,
                              void* d_out, int out_size) {
    const float* x    = (const float*)d_in[0];
    const void*  ei   = d_in[1];
    const float* W1   = (const float*)d_in[2];
    const float* b1   = (const float*)d_in[3];
    const float* W2   = (const float*)d_in[4];
    const float* b2   = (const float*)d_in[5];
    const float* temp = (const float*)d_in[6];
    float* out = (float*)d_out;

    k_detect<<<1, 32>>>((const int*)ei);
    k_init<<<(N_NODES + 255) / 256, 256>>>();
    k_convert<<<(N_EDGES + 255) / 256, 256>>>(ei);
    k_dinv<<<(N_NODES + 255) / 256, 256>>>();
    k_scan<<<1, 1024>>>();
    k_scatter<<<(N_EDGES + 255) / 256, 256>>>();

    dim3 g1(HIDDEN / 128, (N_NODES + 127) / 128);
    k_gemm1<<<g1, 256>>>(x, W1, b1);
    k_gemm2<<<(N_NODES + 127) / 128, 256>>>(W2, b2, temp);

    const int prop_blocks = (N_NODES * 32 + 255) / 256;
    for (int k = 0; k < KITER; k++)
        k_prop<<<prop_blocks, 256>>>(k & 1, temp, k + 1);

    k_softmax<<<prop_blocks, 256>>>(out);
}

// round 6
// speedup vs baseline: 1.3008x; 1.3008x over previous
#include <cuda_runtime.h>
#include <cuda_bf16.h>
#include <math.h>
#include <stdint.h>

#define N_NODES 100000
#define N_EDGES 3200000
#define NFEAT   512
#define HIDDEN  256
#define NCLASS  64
#define KITER   10
#define M_PAD   100096   // 782 * 128

// ---------------- device scratch (no allocations allowed) ----------------
__device__ int    g_is64;
__device__ int    g_ecnt[N_NODES];
__device__ int    g_pos[N_NODES];
__device__ int    g_off[N_NODES + 1];
__device__ float  g_dinv[N_NODES];
__device__ int    g_rowi[N_EDGES];
__device__ int    g_coli[N_EDGES];
__device__ float2 g_edge[N_EDGES];
__device__ __align__(256) __nv_bfloat16 g_xh[(size_t)M_PAD * NFEAT];
__device__ __align__(256) __nv_bfloat16 g_xl[(size_t)M_PAD * NFEAT];
__device__ __align__(256) __nv_bfloat16 g_midh[(size_t)M_PAD * HIDDEN];
__device__ __align__(256) __nv_bfloat16 g_midl[(size_t)M_PAD * HIDDEN];
__device__ __align__(256) __nv_bfloat16 g_B1[(size_t)HIDDEN * (3 * NFEAT)];   // [256][1536]
__device__ __align__(256) __nv_bfloat16 g_B2[(size_t)NCLASS * (3 * HIDDEN)];  // [64][768]
__device__ float  g_h0[(size_t)N_NODES * NCLASS];
__device__ float  g_h1[(size_t)N_NODES * NCLASS];
__device__ float  g_hidden[(size_t)N_NODES * NCLASS];

// ---------------- PTX helpers (baseline PTX only: sm_80-era) ----------------
__device__ __forceinline__ uint32_t smem_u32(const void* p) {
    uint32_t a;
    asm("{ .reg .u64 t; cvta.to.shared.u64 t, %1; cvt.u32.u64 %0, t; }" : "=r"(a) : "l"(p));
    return a;
}
#define CP_ASYNC16(dst, src) \
    asm volatile("cp.async.cg.shared.global [%0], [%1], 16;" :: "r"(dst), "l"(src) : "memory")
#define CP_COMMIT() asm volatile("cp.async.commit_group;" ::: "memory")
#define CP_WAIT1()  asm volatile("cp.async.wait_group 1;" ::: "memory")
#define CP_WAIT0()  asm volatile("cp.async.wait_group 0;" ::: "memory")

#define LDSM_X4(r0, r1, r2, r3, addr)                                         \
    asm volatile("ldmatrix.sync.aligned.m8n8.x4.shared.b16 {%0,%1,%2,%3},[%4];" \
        : "=r"(r0), "=r"(r1), "=r"(r2), "=r"(r3) : "r"(addr))

#define MMA16816(d, a, b)                                                     \
    asm volatile("mma.sync.aligned.m16n8k16.row.col.f32.bf16.bf16.f32 "       \
        "{%0,%1,%2,%3},{%4,%5,%6,%7},{%8,%9},{%0,%1,%2,%3};"                  \
        : "+f"((d)[0]), "+f"((d)[1]), "+f"((d)[2]), "+f"((d)[3])              \
        : "r"((a)[0]), "r"((a)[1]), "r"((a)[2]), "r"((a)[3]),                 \
          "r"((b)[0]), "r"((b)[1]))

// granule swizzle: row stride 128B = 8 granules of 16B
__device__ __forceinline__ uint32_t swz(int row, int kbyte) {
    return (uint32_t)(row * 128 + ((((kbyte >> 4) ^ (row & 7))) << 4) + (kbyte & 15));
}

// ---------------- dtype detection ----------------
__global__ void k_detect(const int* __restrict__ ei32) {
    if (threadIdx.x == 0 && blockIdx.x == 0) {
        int allzero = 1;
        for (int i = 0; i < 64; i++)
            if (ei32[2 * i + 1] != 0) { allzero = 0; break; }
        g_is64 = allzero;
    }
}

// ---------------- preprocessing ----------------
__global__ void k_init() {
    int i = blockIdx.x * blockDim.x + threadIdx.x;
    if (i < N_NODES) { g_ecnt[i] = 0; g_pos[i] = 0; }
}

__global__ void k_convert(const void* __restrict__ ei) {
    int e = blockIdx.x * blockDim.x + threadIdx.x;
    if (e >= N_EDGES) return;
    int r, c;
    if (g_is64) {
        const long long* p = (const long long*)ei;
        r = (int)p[e];
        c = (int)p[(size_t)N_EDGES + e];
    } else {
        const int* p = (const int*)ei;
        r = p[e];
        c = p[(size_t)N_EDGES + e];
    }
    if ((unsigned)r >= N_NODES || (unsigned)c >= N_NODES) { g_rowi[e] = -1; g_coli[e] = -1; return; }
    g_rowi[e] = r;
    g_coli[e] = c;
    atomicAdd(&g_ecnt[c], 1);
}

__global__ void k_dinv() {
    int i = blockIdx.x * blockDim.x + threadIdx.x;
    if (i < N_NODES) g_dinv[i] = rsqrtf((float)(g_ecnt[i] + 1));
}

__global__ void k_scan() {
    __shared__ int warp_sums[32];
    __shared__ int carry_s;
    const int n = N_NODES;
    int tid = threadIdx.x, lane = tid & 31, wid = tid >> 5;
    if (tid == 0) carry_s = 0;
    __syncthreads();
    for (int base = 0; base < n; base += 1024) {
        int i = base + tid;
        int v = (i < n) ? g_ecnt[i] : 0;
        int x = v;
        #pragma unroll
        for (int o = 1; o < 32; o <<= 1) {
            int t = __shfl_up_sync(0xFFFFFFFFu, x, o);
            if (lane >= o) x += t;
        }
        if (lane == 31) warp_sums[wid] = x;
        __syncthreads();
        if (wid == 0) {
            int ws = warp_sums[lane];
            int y = ws;
            #pragma unroll
            for (int o = 1; o < 32; o <<= 1) {
                int t = __shfl_up_sync(0xFFFFFFFFu, y, o);
                if (lane >= o) y += t;
            }
            warp_sums[lane] = y - ws;
        }
        __syncthreads();
        int excl = carry_s + warp_sums[wid] + x - v;
        if (i < n) g_off[i] = excl;
        __syncthreads();
        if (tid == 1023) carry_s = excl + v;
        __syncthreads();
    }
    if (threadIdx.x == 0) g_off[n] = carry_s;
}

__global__ void k_scatter() {
    int e = blockIdx.x * blockDim.x + threadIdx.x;
    if (e >= N_EDGES) return;
    int r = g_rowi[e], c = g_coli[e];
    if (r < 0 || c < 0) return;
    int p = g_off[c] + atomicAdd(&g_pos[c], 1);
    if (p >= N_EDGES) return;
    float w = g_dinv[r] * g_dinv[c];
    g_edge[p] = make_float2(__int_as_float(r), w);
}

// ---------------- bf16 split preprocessing ----------------
__global__ void k_split_x(const float* __restrict__ x) {
    int i = blockIdx.x * blockDim.x + threadIdx.x;
    if (i >= M_PAD * NFEAT) return;
    int row = i >> 9;
    float v = (row < N_NODES) ? x[i] : 0.f;
    __nv_bfloat16 h = __float2bfloat16(v);
    float lo = v - __bfloat162float(h);
    g_xh[i] = h;
    g_xl[i] = __float2bfloat16(lo);
}

__global__ void k_split_w1(const float* __restrict__ W1) {
    int i = blockIdx.x * blockDim.x + threadIdx.x;   // 256 * 1536
    if (i >= HIDDEN * 3 * NFEAT) return;
    int n = i / (3 * NFEAT), k = i % (3 * NFEAT);
    int kk = k % NFEAT;
    bool lo = (k >= NFEAT) && (k < 2 * NFEAT);
    float w = W1[(size_t)kk * HIDDEN + n];
    __nv_bfloat16 h = __float2bfloat16(w);
    g_B1[i] = lo ? __float2bfloat16(w - __bfloat162float(h)) : h;
}

__global__ void k_split_w2(const float* __restrict__ W2) {
    int i = blockIdx.x * blockDim.x + threadIdx.x;   // 64 * 768
    if (i >= NCLASS * 3 * HIDDEN) return;
    int n = i / (3 * HIDDEN), k = i % (3 * HIDDEN);
    int kk = k % HIDDEN;
    bool lo = (k >= HIDDEN) && (k < 2 * HIDDEN);
    float w = W2[(size_t)kk * NCLASS + n];
    __nv_bfloat16 h = __float2bfloat16(w);
    g_B2[i] = lo ? __float2bfloat16(w - __bfloat162float(h)) : h;
}

__global__ void k_zero_pad() {
    int i = blockIdx.x * blockDim.x + threadIdx.x;
    if (i >= (M_PAD - N_NODES) * HIDDEN) return;
    size_t idx = (size_t)N_NODES * HIDDEN + i;
    g_midh[idx] = __float2bfloat16(0.f);
    g_midl[idx] = __float2bfloat16(0.f);
}

// ---------------- GEMM1: mid = relu(x@W1+b1) via mma.sync bf16 ---------------
// C[M_PAD,256] = [xh,xh,xl][M,1536] @ B1^T.  Block 128x128, BK=64, 8 warps 64x32.
__global__ __launch_bounds__(256) void k_mma1(const float* __restrict__ bias) {
    extern __shared__ char sm[];
    uint32_t su = smem_u32(sm);
    const uint32_t ABYTES = 128 * 128;          // 16KB
    const uint32_t BUF = ABYTES + 128 * 128;    // 32KB per stage
    int tid = threadIdx.x, lane = tid & 31, wid = tid >> 5;
    int warp_m = wid & 1;   // 2 warps along M (64 rows each)
    int warp_n = wid >> 1;  // 4 warps along N (32 cols each)
    int rowbase = blockIdx.y * 128;
    int nbase = blockIdx.x * 128;
    float acc[4][4][4] = {};

    auto load_chunk = [&](int c, uint32_t bufu) {
        const __nv_bfloat16* Asrc = (c < 16) ? g_xh : g_xl;
        int acol = (c & 7) * 64;
        #pragma unroll
        for (int g0 = 0; g0 < 1024; g0 += 256) {
            int g = g0 + tid;
            int r = g >> 3, gc = g & 7;
            const void* src = Asrc + (size_t)(rowbase + r) * NFEAT + acol + gc * 8;
            CP_ASYNC16(bufu + swz(r, gc * 16), src);
        }
        #pragma unroll
        for (int g0 = 0; g0 < 1024; g0 += 256) {
            int g = g0 + tid;
            int n = g >> 3, gc = g & 7;
            const void* src = g_B1 + (size_t)(nbase + n) * 1536 + c * 64 + gc * 8;
            CP_ASYNC16(bufu + ABYTES + swz(n, gc * 16), src);
        }
    };

    auto compute = [&](uint32_t bufu) {
        uint32_t Au = bufu, Bu = bufu + ABYTES;
        #pragma unroll
        for (int kk = 0; kk < 4; kk++) {
            uint32_t a[4][4], b[4][2];
            #pragma unroll
            for (int mi = 0; mi < 4; mi++) {
                int row = warp_m * 64 + mi * 16 + (lane & 15);
                int kb = kk * 32 + ((lane >> 4) << 4);
                LDSM_X4(a[mi][0], a[mi][1], a[mi][2], a[mi][3], Au + swz(row, kb));
            }
            #pragma unroll
            for (int nj = 0; nj < 2; nj++) {
                int n = warp_n * 32 + nj * 16 + (lane & 7) + ((lane & 16) ? 8 : 0);
                int kb = kk * 32 + ((lane & 8) ? 16 : 0);
                uint32_t r0, r1, r2, r3;
                LDSM_X4(r0, r1, r2, r3, Bu + swz(n, kb));
                b[nj * 2][0] = r0;     b[nj * 2][1] = r1;
                b[nj * 2 + 1][0] = r2; b[nj * 2 + 1][1] = r3;
            }
            #pragma unroll
            for (int mi = 0; mi < 4; mi++)
                #pragma unroll
                for (int ni = 0; ni < 4; ni++)
                    MMA16816(acc[mi][ni], a[mi], b[ni]);
        }
    };

    load_chunk(0, su);
    CP_COMMIT();
    for (int c = 0; c < 24; c++) {
        if (c + 1 < 24) {
            load_chunk(c + 1, su + ((c + 1) & 1) * BUF);
            CP_COMMIT();
            CP_WAIT1();
        } else {
            CP_WAIT0();
        }
        __syncthreads();
        compute(su + (c & 1) * BUF);
        __syncthreads();
    }

    // epilogue: bias + relu + split hi/lo -> g_midh/g_midl
    int col0 = nbase + warp_n * 32;
    #pragma unroll
    for (int mi = 0; mi < 4; mi++) {
        #pragma unroll
        for (int h = 0; h < 2; h++) {
            int r = rowbase + warp_m * 64 + mi * 16 + (lane >> 2) + h * 8;
            if (r < N_NODES) {
                #pragma unroll
                for (int ni = 0; ni < 4; ni++) {
                    int col = col0 + ni * 8 + (lane & 3) * 2;
                    float v0 = acc[mi][ni][2 * h]     + __ldg(&bias[col]);
                    float v1 = acc[mi][ni][2 * h + 1] + __ldg(&bias[col + 1]);
                    v0 = fmaxf(v0, 0.f);
                    v1 = fmaxf(v1, 0.f);
                    __nv_bfloat162 hh = __floats2bfloat162_rn(v0, v1);
                    __nv_bfloat162 ll = __floats2bfloat162_rn(v0 - __bfloat162float(hh.x),
                                                              v1 - __bfloat162float(hh.y));
                    *(uint32_t*)&g_midh[(size_t)r * HIDDEN + col] = *(uint32_t*)&hh;
                    *(uint32_t*)&g_midl[(size_t)r * HIDDEN + col] = *(uint32_t*)&ll;
                }
            }
        }
    }
}

// ---------------- GEMM2: h0 = mid@W2+b2 ; hidden = temp[0]*h0 ----------------
// Block 128x64, BK=64, 8 warps 32x32 (4x2).
__global__ __launch_bounds__(256) void k_mma2(const float* __restrict__ bias,
                                              const float* __restrict__ temp) {
    extern __shared__ char sm[];
    uint32_t su = smem_u32(sm);
    const uint32_t ABYTES = 128 * 128;          // 16KB
    const uint32_t BUF = ABYTES + 64 * 128;     // 24KB per stage
    int tid = threadIdx.x, lane = tid & 31, wid = tid >> 5;
    int warp_m = wid >> 1;  // 4 warps along M (32 rows each)
    int warp_n = wid & 1;   // 2 warps along N (32 cols each)
    int rowbase = blockIdx.y * 128;
    float acc[2][4][4] = {};

    auto load_chunk = [&](int c, uint32_t bufu) {
        const __nv_bfloat16* Asrc = (c < 8) ? g_midh : g_midl;
        int acol = (c & 3) * 64;
        #pragma unroll
        for (int g0 = 0; g0 < 1024; g0 += 256) {
            int g = g0 + tid;
            int r = g >> 3, gc = g & 7;
            const void* src = Asrc + (size_t)(rowbase + r) * HIDDEN + acol + gc * 8;
            CP_ASYNC16(bufu + swz(r, gc * 16), src);
        }
        {
            int g = tid, n = g >> 3, gc = g & 7;      // 512 granules, 2 per thread
            const void* src = g_B2 + (size_t)n * 768 + c * 64 + gc * 8;
            CP_ASYNC16(bufu + ABYTES + swz(n, gc * 16), src);
            g = tid + 256; n = g >> 3; gc = g & 7;
            src = g_B2 + (size_t)n * 768 + c * 64 + gc * 8;
            CP_ASYNC16(bufu + ABYTES + swz(n, gc * 16), src);
        }
    };

    auto compute = [&](uint32_t bufu) {
        uint32_t Au = bufu, Bu = bufu + ABYTES;
        #pragma unroll
        for (int kk = 0; kk < 4; kk++) {
            uint32_t a[2][4], b[4][2];
            #pragma unroll
            for (int mi = 0; mi < 2; mi++) {
                int row = warp_m * 32 + mi * 16 + (lane & 15);
                int kb = kk * 32 + ((lane >> 4) << 4);
                LDSM_X4(a[mi][0], a[mi][1], a[mi][2], a[mi][3], Au + swz(row, kb));
            }
            #pragma unroll
            for (int nj = 0; nj < 2; nj++) {
                int n = warp_n * 32 + nj * 16 + (lane & 7) + ((lane & 16) ? 8 : 0);
                int kb = kk * 32 + ((lane & 8) ? 16 : 0);
                uint32_t r0, r1, r2, r3;
                LDSM_X4(r0, r1, r2, r3, Bu + swz(n, kb));
                b[nj * 2][0] = r0;     b[nj * 2][1] = r1;
                b[nj * 2 + 1][0] = r2; b[nj * 2 + 1][1] = r3;
            }
            #pragma unroll
            for (int mi = 0; mi < 2; mi++)
                #pragma unroll
                for (int ni = 0; ni < 4; ni++)
                    MMA16816(acc[mi][ni], a[mi], b[ni]);
        }
    };

    load_chunk(0, su);
    CP_COMMIT();
    for (int c = 0; c < 12; c++) {
        if (c + 1 < 12) {
            load_chunk(c + 1, su + ((c + 1) & 1) * BUF);
            CP_COMMIT();
            CP_WAIT1();
        } else {
            CP_WAIT0();
        }
        __syncthreads();
        compute(su + (c & 1) * BUF);
        __syncthreads();
    }

    float t0 = __ldg(&temp[0]);
    #pragma unroll
    for (int mi = 0; mi < 2; mi++) {
        #pragma unroll
        for (int h = 0; h < 2; h++) {
            int r = rowbase + warp_m * 32 + mi * 16 + (lane >> 2) + h * 8;
            if (r < N_NODES) {
                #pragma unroll
                for (int ni = 0; ni < 4; ni++) {
                    int col = warp_n * 32 + ni * 8 + (lane & 3) * 2;
                    float v0 = acc[mi][ni][2 * h]     + __ldg(&bias[col]);
                    float v1 = acc[mi][ni][2 * h + 1] + __ldg(&bias[col + 1]);
                    *(float2*)&g_h0[(size_t)r * NCLASS + col] = make_float2(v0, v1);
                    *(float2*)&g_hidden[(size_t)r * NCLASS + col] = make_float2(t0 * v0, t0 * v1);
                }
            }
        }
    }
}

// ---------------- propagation ----------------
__global__ __launch_bounds__(256) void k_prop(int parity,
                                              const float* __restrict__ temp,
                                              int kidx) {
    int t = blockIdx.x * blockDim.x + threadIdx.x;
    int c = t >> 5, lane = t & 31;
    if (c >= N_NODES) return;
    const float* hin = parity ? g_h1 : g_h0;
    float*       hout = parity ? g_h0 : g_h1;
    const float2* hin2 = (const float2*)hin;

    float dc = g_dinv[c];
    float sw = dc * dc;
    float2 v = hin2[(size_t)c * 32 + lane];
    float2 acc;
    acc.x = sw * v.x;
    acc.y = sw * v.y;

    int b = g_off[c], e = g_off[c + 1];
    for (int p = b; p < e; p++) {
        float2 ed = __ldg(&g_edge[p]);
        int s = __float_as_int(ed.x);
        float w = ed.y;
        float2 hv = hin2[(size_t)s * 32 + lane];
        acc.x = fmaf(w, hv.x, acc.x);
        acc.y = fmaf(w, hv.y, acc.y);
    }
    ((float2*)hout)[(size_t)c * 32 + lane] = acc;

    float tk = temp[kidx];
    float2* hid2 = (float2*)g_hidden;
    float2 h = hid2[(size_t)c * 32 + lane];
    h.x = fmaf(tk, acc.x, h.x);
    h.y = fmaf(tk, acc.y, h.y);
    hid2[(size_t)c * 32 + lane] = h;
}

// ---------------- log_softmax ----------------
__global__ __launch_bounds__(256) void k_softmax(float* __restrict__ out) {
    int t = blockIdx.x * blockDim.x + threadIdx.x;
    int r = t >> 5, lane = t & 31;
    if (r >= N_NODES) return;
    const float2* h2 = (const float2*)g_hidden;
    float2 v = h2[(size_t)r * 32 + lane];
    float m = fmaxf(v.x, v.y);
    #pragma unroll
    for (int o = 16; o > 0; o >>= 1) m = fmaxf(m, __shfl_xor_sync(0xFFFFFFFFu, m, o));
    float s = expf(v.x - m) + expf(v.y - m);
    #pragma unroll
    for (int o = 16; o > 0; o >>= 1) s += __shfl_xor_sync(0xFFFFFFFFu, s, o);
    float ls = m + logf(s);
    float2 o2;
    o2.x = v.x - ls;
    o2.y = v.y - ls;
    ((float2*)out)[(size_t)r * 32 + lane] = o2;
}

// ---------------- driver ----------------
extern "C" void kernel_launch(void* const* d_in, const int* in_sizes, int n_in,
                              void* d_out, int out_size) {
    const float* x    = (const float*)d_in[0];
    const void*  ei   = d_in[1];
    const float* W1   = (const float*)d_in[2];
    const float* b1   = (const float*)d_in[3];
    const float* W2   = (const float*)d_in[4];
    const float* b2   = (const float*)d_in[5];
    const float* temp = (const float*)d_in[6];
    float* out = (float*)d_out;

    const int SMEM1 = 2 * (128 * 128 + 128 * 128);  // 65536
    const int SMEM2 = 2 * (128 * 128 + 64 * 128);   // 49152
    cudaFuncSetAttribute(k_mma1, cudaFuncAttributeMaxDynamicSharedMemorySize, SMEM1);
    cudaFuncSetAttribute(k_mma2, cudaFuncAttributeMaxDynamicSharedMemorySize, SMEM2);

    k_detect<<<1, 32>>>((const int*)ei);
    k_init<<<(N_NODES + 255) / 256, 256>>>();
    k_convert<<<(N_EDGES + 255) / 256, 256>>>(ei);
    k_dinv<<<(N_NODES + 255) / 256, 256>>>();
    k_scan<<<1, 1024>>>();
    k_scatter<<<(N_EDGES + 255) / 256, 256>>>();

    k_split_x<<<(M_PAD * NFEAT + 255) / 256, 256>>>(x);
    k_split_w1<<<(HIDDEN * 3 * NFEAT + 255) / 256, 256>>>(W1);
    k_split_w2<<<(NCLASS * 3 * HIDDEN + 255) / 256, 256>>>(W2);
    k_zero_pad<<<((M_PAD - N_NODES) * HIDDEN + 255) / 256, 256>>>();

    k_mma1<<<dim3(2, M_PAD / 128), 256, SMEM1>>>(b1);
    k_mma2<<<dim3(1, M_PAD / 128), 256, SMEM2>>>(b2, temp);

    const int prop_blocks = (N_NODES * 32 + 255) / 256;
    for (int k = 0; k < KITER; k++)
        k_prop<<<prop_blocks, 256>>>(k & 1, temp, k + 1);

    k_softmax<<<prop_blocks, 256>>>(out);
}

// round 7
// speedup vs baseline: 1.3638x; 1.0484x over previous
#include <cuda_runtime.h>
#include <cuda_bf16.h>
#include <cuda_fp16.h>
#include <math.h>
#include <stdint.h>

#define N_NODES 100000
#define N_EDGES 3200000
#define NFEAT   512
#define HIDDEN  256
#define NCLASS  64
#define KITER   10
#define M_PAD   100096   // 782 * 128

// ---------------- device scratch (no allocations allowed) ----------------
__device__ int    g_is64;
__device__ int    g_ecnt[N_NODES];
__device__ int    g_pos[N_NODES];
__device__ int    g_off[N_NODES + 1];
__device__ float  g_dinv[N_NODES];
__device__ int    g_rowi[N_EDGES];
__device__ int    g_coli[N_EDGES];
__device__ float2 g_edge[N_EDGES];
__device__ __align__(256) __nv_bfloat16 g_xh[(size_t)M_PAD * NFEAT];
__device__ __align__(256) __nv_bfloat16 g_xl[(size_t)M_PAD * NFEAT];
__device__ __align__(256) __nv_bfloat16 g_midh[(size_t)M_PAD * HIDDEN];
__device__ __align__(256) __nv_bfloat16 g_midl[(size_t)M_PAD * HIDDEN];
__device__ __align__(256) __nv_bfloat16 g_B1[(size_t)HIDDEN * (3 * NFEAT)];   // [256][1536]
__device__ __align__(256) __nv_bfloat16 g_B2[(size_t)NCLASS * (3 * HIDDEN)];  // [64][768]
__device__ __align__(256) __half g_h0[(size_t)N_NODES * NCLASS];   // fp16 prop state
__device__ __align__(256) __half g_h1[(size_t)N_NODES * NCLASS];
__device__ float  g_hidden[(size_t)N_NODES * NCLASS];

// ---------------- PTX helpers (baseline PTX only: sm_80-era) ----------------
__device__ __forceinline__ uint32_t smem_u32(const void* p) {
    uint32_t a;
    asm("{ .reg .u64 t; cvta.to.shared.u64 t, %1; cvt.u32.u64 %0, t; }" : "=r"(a) : "l"(p));
    return a;
}
#define CP_ASYNC16(dst, src) \
    asm volatile("cp.async.cg.shared.global [%0], [%1], 16;" :: "r"(dst), "l"(src) : "memory")
#define CP_COMMIT() asm volatile("cp.async.commit_group;" ::: "memory")
#define CP_WAIT1()  asm volatile("cp.async.wait_group 1;" ::: "memory")
#define CP_WAIT0()  asm volatile("cp.async.wait_group 0;" ::: "memory")

#define LDSM_X4(r0, r1, r2, r3, addr)                                         \
    asm volatile("ldmatrix.sync.aligned.m8n8.x4.shared.b16 {%0,%1,%2,%3},[%4];" \
        : "=r"(r0), "=r"(r1), "=r"(r2), "=r"(r3) : "r"(addr))

#define MMA16816(d, a, b)                                                     \
    asm volatile("mma.sync.aligned.m16n8k16.row.col.f32.bf16.bf16.f32 "       \
        "{%0,%1,%2,%3},{%4,%5,%6,%7},{%8,%9},{%0,%1,%2,%3};"                  \
        : "+f"((d)[0]), "+f"((d)[1]), "+f"((d)[2]), "+f"((d)[3])              \
        : "r"((a)[0]), "r"((a)[1]), "r"((a)[2]), "r"((a)[3]),                 \
          "r"((b)[0]), "r"((b)[1]))

// granule swizzle: row stride 128B = 8 granules of 16B
__device__ __forceinline__ uint32_t swz(int row, int kbyte) {
    return (uint32_t)(row * 128 + ((((kbyte >> 4) ^ (row & 7))) << 4) + (kbyte & 15));
}

// ---------------- dtype detection ----------------
__global__ void k_detect(const int* __restrict__ ei32) {
    if (threadIdx.x == 0 && blockIdx.x == 0) {
        int allzero = 1;
        for (int i = 0; i < 64; i++)
            if (ei32[2 * i + 1] != 0) { allzero = 0; break; }
        g_is64 = allzero;
    }
}

// ---------------- preprocessing ----------------
__global__ void k_init() {
    int i = blockIdx.x * blockDim.x + threadIdx.x;
    if (i < N_NODES) { g_ecnt[i] = 0; g_pos[i] = 0; }
}

__global__ void k_convert(const void* __restrict__ ei) {
    int e = blockIdx.x * blockDim.x + threadIdx.x;
    if (e >= N_EDGES) return;
    int r, c;
    if (g_is64) {
        const long long* p = (const long long*)ei;
        r = (int)p[e];
        c = (int)p[(size_t)N_EDGES + e];
    } else {
        const int* p = (const int*)ei;
        r = p[e];
        c = p[(size_t)N_EDGES + e];
    }
    if ((unsigned)r >= N_NODES || (unsigned)c >= N_NODES) { g_rowi[e] = -1; g_coli[e] = -1; return; }
    g_rowi[e] = r;
    g_coli[e] = c;
    atomicAdd(&g_ecnt[c], 1);
}

__global__ void k_dinv() {
    int i = blockIdx.x * blockDim.x + threadIdx.x;
    if (i < N_NODES) g_dinv[i] = rsqrtf((float)(g_ecnt[i] + 1));
}

__global__ void k_scan() {
    __shared__ int warp_sums[32];
    __shared__ int carry_s;
    const int n = N_NODES;
    int tid = threadIdx.x, lane = tid & 31, wid = tid >> 5;
    if (tid == 0) carry_s = 0;
    __syncthreads();
    for (int base = 0; base < n; base += 1024) {
        int i = base + tid;
        int v = (i < n) ? g_ecnt[i] : 0;
        int x = v;
        #pragma unroll
        for (int o = 1; o < 32; o <<= 1) {
            int t = __shfl_up_sync(0xFFFFFFFFu, x, o);
            if (lane >= o) x += t;
        }
        if (lane == 31) warp_sums[wid] = x;
        __syncthreads();
        if (wid == 0) {
            int ws = warp_sums[lane];
            int y = ws;
            #pragma unroll
            for (int o = 1; o < 32; o <<= 1) {
                int t = __shfl_up_sync(0xFFFFFFFFu, y, o);
                if (lane >= o) y += t;
            }
            warp_sums[lane] = y - ws;
        }
        __syncthreads();
        int excl = carry_s + warp_sums[wid] + x - v;
        if (i < n) g_off[i] = excl;
        __syncthreads();
        if (tid == 1023) carry_s = excl + v;
        __syncthreads();
    }
    if (threadIdx.x == 0) g_off[n] = carry_s;
}

__global__ void k_scatter() {
    int e = blockIdx.x * blockDim.x + threadIdx.x;
    if (e >= N_EDGES) return;
    int r = g_rowi[e], c = g_coli[e];
    if (r < 0 || c < 0) return;
    int p = g_off[c] + atomicAdd(&g_pos[c], 1);
    if (p >= N_EDGES) return;
    float w = g_dinv[r] * g_dinv[c];
    g_edge[p] = make_float2(__int_as_float(r), w);
}

// ---------------- bf16 split preprocessing ----------------
__global__ void k_split_x(const float* __restrict__ x) {
    int i = blockIdx.x * blockDim.x + threadIdx.x;
    if (i >= M_PAD * NFEAT) return;
    int row = i >> 9;
    float v = (row < N_NODES) ? x[i] : 0.f;
    __nv_bfloat16 h = __float2bfloat16(v);
    float lo = v - __bfloat162float(h);
    g_xh[i] = h;
    g_xl[i] = __float2bfloat16(lo);
}

__global__ void k_split_w1(const float* __restrict__ W1) {
    int i = blockIdx.x * blockDim.x + threadIdx.x;   // 256 * 1536
    if (i >= HIDDEN * 3 * NFEAT) return;
    int n = i / (3 * NFEAT), k = i % (3 * NFEAT);
    int kk = k % NFEAT;
    bool lo = (k >= NFEAT) && (k < 2 * NFEAT);
    float w = W1[(size_t)kk * HIDDEN + n];
    __nv_bfloat16 h = __float2bfloat16(w);
    g_B1[i] = lo ? __float2bfloat16(w - __bfloat162float(h)) : h;
}

__global__ void k_split_w2(const float* __restrict__ W2) {
    int i = blockIdx.x * blockDim.x + threadIdx.x;   // 64 * 768
    if (i >= NCLASS * 3 * HIDDEN) return;
    int n = i / (3 * HIDDEN), k = i % (3 * HIDDEN);
    int kk = k % HIDDEN;
    bool lo = (k >= HIDDEN) && (k < 2 * HIDDEN);
    float w = W2[(size_t)kk * NCLASS + n];
    __nv_bfloat16 h = __float2bfloat16(w);
    g_B2[i] = lo ? __float2bfloat16(w - __bfloat162float(h)) : h;
}

__global__ void k_zero_pad() {
    int i = blockIdx.x * blockDim.x + threadIdx.x;
    if (i >= (M_PAD - N_NODES) * HIDDEN) return;
    size_t idx = (size_t)N_NODES * HIDDEN + i;
    g_midh[idx] = __float2bfloat16(0.f);
    g_midl[idx] = __float2bfloat16(0.f);
}

// ---------------- GEMM1: mid = relu(x@W1+b1) via mma.sync bf16 ---------------
__global__ __launch_bounds__(256) void k_mma1(const float* __restrict__ bias) {
    extern __shared__ char sm[];
    uint32_t su = smem_u32(sm);
    const uint32_t ABYTES = 128 * 128;          // 16KB
    const uint32_t BUF = ABYTES + 128 * 128;    // 32KB per stage
    int tid = threadIdx.x, lane = tid & 31, wid = tid >> 5;
    int warp_m = wid & 1;
    int warp_n = wid >> 1;
    int rowbase = blockIdx.y * 128;
    int nbase = blockIdx.x * 128;
    float acc[4][4][4] = {};

    auto load_chunk = [&](int c, uint32_t bufu) {
        const __nv_bfloat16* Asrc = (c < 16) ? g_xh : g_xl;
        int acol = (c & 7) * 64;
        #pragma unroll
        for (int g0 = 0; g0 < 1024; g0 += 256) {
            int g = g0 + tid;
            int r = g >> 3, gc = g & 7;
            const void* src = Asrc + (size_t)(rowbase + r) * NFEAT + acol + gc * 8;
            CP_ASYNC16(bufu + swz(r, gc * 16), src);
        }
        #pragma unroll
        for (int g0 = 0; g0 < 1024; g0 += 256) {
            int g = g0 + tid;
            int n = g >> 3, gc = g & 7;
            const void* src = g_B1 + (size_t)(nbase + n) * 1536 + c * 64 + gc * 8;
            CP_ASYNC16(bufu + ABYTES + swz(n, gc * 16), src);
        }
    };

    auto compute = [&](uint32_t bufu) {
        uint32_t Au = bufu, Bu = bufu + ABYTES;
        #pragma unroll
        for (int kk = 0; kk < 4; kk++) {
            uint32_t a[4][4], b[4][2];
            #pragma unroll
            for (int mi = 0; mi < 4; mi++) {
                int row = warp_m * 64 + mi * 16 + (lane & 15);
                int kb = kk * 32 + ((lane >> 4) << 4);
                LDSM_X4(a[mi][0], a[mi][1], a[mi][2], a[mi][3], Au + swz(row, kb));
            }
            #pragma unroll
            for (int nj = 0; nj < 2; nj++) {
                int n = warp_n * 32 + nj * 16 + (lane & 7) + ((lane & 16) ? 8 : 0);
                int kb = kk * 32 + ((lane & 8) ? 16 : 0);
                uint32_t r0, r1, r2, r3;
                LDSM_X4(r0, r1, r2, r3, Bu + swz(n, kb));
                b[nj * 2][0] = r0;     b[nj * 2][1] = r1;
                b[nj * 2 + 1][0] = r2; b[nj * 2 + 1][1] = r3;
            }
            #pragma unroll
            for (int mi = 0; mi < 4; mi++)
                #pragma unroll
                for (int ni = 0; ni < 4; ni++)
                    MMA16816(acc[mi][ni], a[mi], b[ni]);
        }
    };

    load_chunk(0, su);
    CP_COMMIT();
    for (int c = 0; c < 24; c++) {
        if (c + 1 < 24) {
            load_chunk(c + 1, su + ((c + 1) & 1) * BUF);
            CP_COMMIT();
            CP_WAIT1();
        } else {
            CP_WAIT0();
        }
        __syncthreads();
        compute(su + (c & 1) * BUF);
        __syncthreads();
    }

    int col0 = nbase + warp_n * 32;
    #pragma unroll
    for (int mi = 0; mi < 4; mi++) {
        #pragma unroll
        for (int h = 0; h < 2; h++) {
            int r = rowbase + warp_m * 64 + mi * 16 + (lane >> 2) + h * 8;
            if (r < N_NODES) {
                #pragma unroll
                for (int ni = 0; ni < 4; ni++) {
                    int col = col0 + ni * 8 + (lane & 3) * 2;
                    float v0 = acc[mi][ni][2 * h]     + __ldg(&bias[col]);
                    float v1 = acc[mi][ni][2 * h + 1] + __ldg(&bias[col + 1]);
                    v0 = fmaxf(v0, 0.f);
                    v1 = fmaxf(v1, 0.f);
                    __nv_bfloat162 hh = __floats2bfloat162_rn(v0, v1);
                    __nv_bfloat162 ll = __floats2bfloat162_rn(v0 - __bfloat162float(hh.x),
                                                              v1 - __bfloat162float(hh.y));
                    *(uint32_t*)&g_midh[(size_t)r * HIDDEN + col] = *(uint32_t*)&hh;
                    *(uint32_t*)&g_midl[(size_t)r * HIDDEN + col] = *(uint32_t*)&ll;
                }
            }
        }
    }
}

// ---------------- GEMM2: h0 = mid@W2+b2 (fp16) ; hidden = temp[0]*h0 (fp32) --
__global__ __launch_bounds__(256) void k_mma2(const float* __restrict__ bias,
                                              const float* __restrict__ temp) {
    extern __shared__ char sm[];
    uint32_t su = smem_u32(sm);
    const uint32_t ABYTES = 128 * 128;
    const uint32_t BUF = ABYTES + 64 * 128;
    int tid = threadIdx.x, lane = tid & 31, wid = tid >> 5;
    int warp_m = wid >> 1;
    int warp_n = wid & 1;
    int rowbase = blockIdx.y * 128;
    float acc[2][4][4] = {};

    auto load_chunk = [&](int c, uint32_t bufu) {
        const __nv_bfloat16* Asrc = (c < 8) ? g_midh : g_midl;
        int acol = (c & 3) * 64;
        #pragma unroll
        for (int g0 = 0; g0 < 1024; g0 += 256) {
            int g = g0 + tid;
            int r = g >> 3, gc = g & 7;
            const void* src = Asrc + (size_t)(rowbase + r) * HIDDEN + acol + gc * 8;
            CP_ASYNC16(bufu + swz(r, gc * 16), src);
        }
        {
            int g = tid, n = g >> 3, gc = g & 7;
            const void* src = g_B2 + (size_t)n * 768 + c * 64 + gc * 8;
            CP_ASYNC16(bufu + ABYTES + swz(n, gc * 16), src);
            g = tid + 256; n = g >> 3; gc = g & 7;
            src = g_B2 + (size_t)n * 768 + c * 64 + gc * 8;
            CP_ASYNC16(bufu + ABYTES + swz(n, gc * 16), src);
        }
    };

    auto compute = [&](uint32_t bufu) {
        uint32_t Au = bufu, Bu = bufu + ABYTES;
        #pragma unroll
        for (int kk = 0; kk < 4; kk++) {
            uint32_t a[2][4], b[4][2];
            #pragma unroll
            for (int mi = 0; mi < 2; mi++) {
                int row = warp_m * 32 + mi * 16 + (lane & 15);
                int kb = kk * 32 + ((lane >> 4) << 4);
                LDSM_X4(a[mi][0], a[mi][1], a[mi][2], a[mi][3], Au + swz(row, kb));
            }
            #pragma unroll
            for (int nj = 0; nj < 2; nj++) {
                int n = warp_n * 32 + nj * 16 + (lane & 7) + ((lane & 16) ? 8 : 0);
                int kb = kk * 32 + ((lane & 8) ? 16 : 0);
                uint32_t r0, r1, r2, r3;
                LDSM_X4(r0, r1, r2, r3, Bu + swz(n, kb));
                b[nj * 2][0] = r0;     b[nj * 2][1] = r1;
                b[nj * 2 + 1][0] = r2; b[nj * 2 + 1][1] = r3;
            }
            #pragma unroll
            for (int mi = 0; mi < 2; mi++)
                #pragma unroll
                for (int ni = 0; ni < 4; ni++)
                    MMA16816(acc[mi][ni], a[mi], b[ni]);
        }
    };

    load_chunk(0, su);
    CP_COMMIT();
    for (int c = 0; c < 12; c++) {
        if (c + 1 < 12) {
            load_chunk(c + 1, su + ((c + 1) & 1) * BUF);
            CP_COMMIT();
            CP_WAIT1();
        } else {
            CP_WAIT0();
        }
        __syncthreads();
        compute(su + (c & 1) * BUF);
        __syncthreads();
    }

    float t0 = __ldg(&temp[0]);
    #pragma unroll
    for (int mi = 0; mi < 2; mi++) {
        #pragma unroll
        for (int h = 0; h < 2; h++) {
            int r = rowbase + warp_m * 32 + mi * 16 + (lane >> 2) + h * 8;
            if (r < N_NODES) {
                #pragma unroll
                for (int ni = 0; ni < 4; ni++) {
                    int col = warp_n * 32 + ni * 8 + (lane & 3) * 2;
                    float v0 = acc[mi][ni][2 * h]     + __ldg(&bias[col]);
                    float v1 = acc[mi][ni][2 * h + 1] + __ldg(&bias[col + 1]);
                    *(__half2*)&g_h0[(size_t)r * NCLASS + col] = __floats2half2_rn(v0, v1);
                    *(float2*)&g_hidden[(size_t)r * NCLASS + col] = make_float2(t0 * v0, t0 * v1);
                }
            }
        }
    }
}

// ---------------- propagation: fp16 gather; last iter fuses log_softmax -----
__global__ __launch_bounds__(256) void k_prop(int parity,
                                              const float* __restrict__ temp,
                                              int kidx, int last,
                                              float* __restrict__ out) {
    int t = blockIdx.x * blockDim.x + threadIdx.x;
    int c = t >> 5, lane = t & 31;
    if (c >= N_NODES) return;
    const __half2* hin2 = (const __half2*)(parity ? g_h1 : g_h0);
    __half2*       hout2 = (__half2*)(parity ? g_h0 : g_h1);

    float dc = g_dinv[c];
    float sw = dc * dc;
    float2 v = __half22float2(hin2[(size_t)c * 32 + lane]);
    float2 acc;
    acc.x = sw * v.x;
    acc.y = sw * v.y;

    int b = g_off[c], e = g_off[c + 1];
    for (int p = b; p < e; p++) {
        float2 ed = __ldg(&g_edge[p]);
        int s = __float_as_int(ed.x);
        float w = ed.y;
        float2 hv = __half22float2(hin2[(size_t)s * 32 + lane]);   // 128B L2 line gather
        acc.x = fmaf(w, hv.x, acc.x);
        acc.y = fmaf(w, hv.y, acc.y);
    }

    float tk = temp[kidx];
    float2* hid2 = (float2*)g_hidden;
    float2 h = hid2[(size_t)c * 32 + lane];
    h.x = fmaf(tk, acc.x, h.x);
    h.y = fmaf(tk, acc.y, h.y);

    if (!last) {
        hout2[(size_t)c * 32 + lane] = __floats2half2_rn(acc.x, acc.y);
        hid2[(size_t)c * 32 + lane] = h;
    } else {
        // fused log_softmax over the 64 final hidden values of this node
        float m = fmaxf(h.x, h.y);
        #pragma unroll
        for (int o = 16; o > 0; o >>= 1) m = fmaxf(m, __shfl_xor_sync(0xFFFFFFFFu, m, o));
        float s = expf(h.x - m) + expf(h.y - m);
        #pragma unroll
        for (int o = 16; o > 0; o >>= 1) s += __shfl_xor_sync(0xFFFFFFFFu, s, o);
        float ls = m + logf(s);
        ((float2*)out)[(size_t)c * 32 + lane] = make_float2(h.x - ls, h.y - ls);
    }
}

// ---------------- driver ----------------
extern "C" void kernel_launch(void* const* d_in, const int* in_sizes, int n_in,
                              void* d_out, int out_size) {
    const float* x    = (const float*)d_in[0];
    const void*  ei   = d_in[1];
    const float* W1   = (const float*)d_in[2];
    const float* b1   = (const float*)d_in[3];
    const float* W2   = (const float*)d_in[4];
    const float* b2   = (const float*)d_in[5];
    const float* temp = (const float*)d_in[6];
    float* out = (float*)d_out;

    const int SMEM1 = 2 * (128 * 128 + 128 * 128);  // 65536
    const int SMEM2 = 2 * (128 * 128 + 64 * 128);   // 49152
    cudaFuncSetAttribute(k_mma1, cudaFuncAttributeMaxDynamicSharedMemorySize, SMEM1);
    cudaFuncSetAttribute(k_mma2, cudaFuncAttributeMaxDynamicSharedMemorySize, SMEM2);

    k_detect<<<1, 32>>>((const int*)ei);
    k_init<<<(N_NODES + 255) / 256, 256>>>();
    k_convert<<<(N_EDGES + 255) / 256, 256>>>(ei);
    k_dinv<<<(N_NODES + 255) / 256, 256>>>();
    k_scan<<<1, 1024>>>();
    k_scatter<<<(N_EDGES + 255) / 256, 256>>>();

    k_split_x<<<(M_PAD * NFEAT + 255) / 256, 256>>>(x);
    k_split_w1<<<(HIDDEN * 3 * NFEAT + 255) / 256, 256>>>(W1);
    k_split_w2<<<(NCLASS * 3 * HIDDEN + 255) / 256, 256>>>(W2);
    k_zero_pad<<<((M_PAD - N_NODES) * HIDDEN + 255) / 256, 256>>>();

    k_mma1<<<dim3(2, M_PAD / 128), 256, SMEM1>>>(b1);
    k_mma2<<<dim3(1, M_PAD / 128), 256, SMEM2>>>(b2, temp);

    const int prop_blocks = (N_NODES * 32 + 255) / 256;
    for (int k = 0; k < KITER; k++)
        k_prop<<<prop_blocks, 256>>>(k & 1, temp, k + 1, (k == KITER - 1) ? 1 : 0, out);
}

// round 8
// speedup vs baseline: 1.5564x; 1.1413x over previous
#include <cuda_runtime.h>
#include <cuda_bf16.h>
#include <cuda_fp16.h>
#include <math.h>
#include <stdint.h>

#define N_NODES 100000
#define N_EDGES 3200000
#define NFEAT   512
#define HIDDEN  256
#define NCLASS  64
#define KITER   10
#define M_PAD   100096   // 782 * 128

// ---------------- device scratch (no allocations allowed) ----------------
__device__ int    g_is64;
__device__ int    g_ecnt[N_NODES];
__device__ int    g_pos[N_NODES];
__device__ int    g_off[N_NODES + 1];
__device__ float  g_dinv[N_NODES];
__device__ int    g_rowi[N_EDGES];
__device__ int    g_coli[N_EDGES];
__device__ float2 g_edge[N_EDGES];
__device__ __align__(256) __nv_bfloat16 g_B1[(size_t)HIDDEN * 1024];  // [256][1024]: W1h|W1l
__device__ __align__(256) __nv_bfloat16 g_B2[(size_t)NCLASS * 512];   // [64][512]:  W2h|W2l
__device__ __align__(256) __half g_h0[(size_t)N_NODES * NCLASS];
__device__ __align__(256) __half g_h1[(size_t)N_NODES * NCLASS];
__device__ float  g_hidden[(size_t)N_NODES * NCLASS];

// ---------------- PTX helpers (baseline PTX only: sm_80-era) ----------------
__device__ __forceinline__ uint32_t smem_u32(const void* p) {
    uint32_t a;
    asm("{ .reg .u64 t; cvta.to.shared.u64 t, %1; cvt.u32.u64 %0, t; }" : "=r"(a) : "l"(p));
    return a;
}
#define CP_ASYNC16(dst, src) \
    asm volatile("cp.async.cg.shared.global [%0], [%1], 16;" :: "r"(dst), "l"(src) : "memory")
#define CP_COMMIT() asm volatile("cp.async.commit_group;" ::: "memory")
#define CP_WAIT1()  asm volatile("cp.async.wait_group 1;" ::: "memory")
#define CP_WAIT0()  asm volatile("cp.async.wait_group 0;" ::: "memory")

#define LDSM_X4(r0, r1, r2, r3, addr)                                         \
    asm volatile("ldmatrix.sync.aligned.m8n8.x4.shared.b16 {%0,%1,%2,%3},[%4];" \
        : "=r"(r0), "=r"(r1), "=r"(r2), "=r"(r3) : "r"(addr))

#define MMA16816(d, a, b)                                                     \
    asm volatile("mma.sync.aligned.m16n8k16.row.col.f32.bf16.bf16.f32 "       \
        "{%0,%1,%2,%3},{%4,%5,%6,%7},{%8,%9},{%0,%1,%2,%3};"                  \
        : "+f"((d)[0]), "+f"((d)[1]), "+f"((d)[2]), "+f"((d)[3])              \
        : "r"((a)[0]), "r"((a)[1]), "r"((a)[2]), "r"((a)[3]),                 \
          "r"((b)[0]), "r"((b)[1]))

// smem layout for fused kernel
#define ST1      49152    // per-stage: x 16K | B1h 16K | B1l 16K
#define XH_OFF   98304
#define XL_OFF   106496
#define MIDH_OFF 0
#define MIDL_OFF 65536
#define B2_OFF   131072   // two 8K buffers
#define SMEMF    147456

// ---------------- dtype detection ----------------
__global__ void k_detect(const int* __restrict__ ei32) {
    if (threadIdx.x == 0 && blockIdx.x == 0) {
        int allzero = 1;
        for (int i = 0; i < 64; i++)
            if (ei32[2 * i + 1] != 0) { allzero = 0; break; }
        g_is64 = allzero;
    }
}

// ---------------- graph preprocessing ----------------
__global__ void k_init() {
    int i = blockIdx.x * blockDim.x + threadIdx.x;
    if (i < N_NODES) { g_ecnt[i] = 0; g_pos[i] = 0; }
}

__global__ void k_convert(const void* __restrict__ ei) {
    int e = blockIdx.x * blockDim.x + threadIdx.x;
    if (e >= N_EDGES) return;
    int r, c;
    if (g_is64) {
        const long long* p = (const long long*)ei;
        r = (int)p[e];
        c = (int)p[(size_t)N_EDGES + e];
    } else {
        const int* p = (const int*)ei;
        r = p[e];
        c = p[(size_t)N_EDGES + e];
    }
    if ((unsigned)r >= N_NODES || (unsigned)c >= N_NODES) { g_rowi[e] = -1; g_coli[e] = -1; return; }
    g_rowi[e] = r;
    g_coli[e] = c;
    atomicAdd(&g_ecnt[c], 1);
}

__global__ void k_dinv() {
    int i = blockIdx.x * blockDim.x + threadIdx.x;
    if (i < N_NODES) g_dinv[i] = rsqrtf((float)(g_ecnt[i] + 1));
}

__global__ void k_scan() {
    __shared__ int warp_sums[32];
    __shared__ int carry_s;
    const int n = N_NODES;
    int tid = threadIdx.x, lane = tid & 31, wid = tid >> 5;
    if (tid == 0) carry_s = 0;
    __syncthreads();
    for (int base = 0; base < n; base += 1024) {
        int i = base + tid;
        int v = (i < n) ? g_ecnt[i] : 0;
        int x = v;
        #pragma unroll
        for (int o = 1; o < 32; o <<= 1) {
            int t = __shfl_up_sync(0xFFFFFFFFu, x, o);
            if (lane >= o) x += t;
        }
        if (lane == 31) warp_sums[wid] = x;
        __syncthreads();
        if (wid == 0) {
            int ws = warp_sums[lane];
            int y = ws;
            #pragma unroll
            for (int o = 1; o < 32; o <<= 1) {
                int t = __shfl_up_sync(0xFFFFFFFFu, y, o);
                if (lane >= o) y += t;
            }
            warp_sums[lane] = y - ws;
        }
        __syncthreads();
        int excl = carry_s + warp_sums[wid] + x - v;
        if (i < n) g_off[i] = excl;
        __syncthreads();
        if (tid == 1023) carry_s = excl + v;
        __syncthreads();
    }
    if (threadIdx.x == 0) g_off[n] = carry_s;
}

__global__ void k_scatter() {
    int e = blockIdx.x * blockDim.x + threadIdx.x;
    if (e >= N_EDGES) return;
    int r = g_rowi[e], c = g_coli[e];
    if (r < 0 || c < 0) return;
    int p = g_off[c] + atomicAdd(&g_pos[c], 1);
    if (p >= N_EDGES) return;
    float w = g_dinv[r] * g_dinv[c];
    g_edge[p] = make_float2(__int_as_float(r), w);
}

// ---------------- weight split preprocessing ----------------
__global__ void k_split_w1(const float* __restrict__ W1) {
    int i = blockIdx.x * blockDim.x + threadIdx.x;   // 256 * 1024
    if (i >= HIDDEN * 1024) return;
    int n = i >> 10, k = i & 1023;
    int kk = k & 511;
    bool lo = k >= 512;
    float w = W1[(size_t)kk * HIDDEN + n];
    __nv_bfloat16 h = __float2bfloat16(w);
    g_B1[i] = lo ? __float2bfloat16(w - __bfloat162float(h)) : h;
}

__global__ void k_split_w2(const float* __restrict__ W2) {
    int i = blockIdx.x * blockDim.x + threadIdx.x;   // 64 * 512
    if (i >= NCLASS * 512) return;
    int n = i >> 9, k = i & 511;
    int kk = k & 255;
    bool lo = k >= 256;
    float w = W2[(size_t)kk * NCLASS + n];
    __nv_bfloat16 h = __float2bfloat16(w);
    g_B2[i] = lo ? __float2bfloat16(w - __bfloat162float(h)) : h;
}

// ---------------- fused MLP: relu(x@W1+b1)@W2+b2, fp32-accurate hi/lo -------
__global__ __launch_bounds__(256) void k_fused(const float* __restrict__ x,
                                               const float* __restrict__ b1,
                                               const float* __restrict__ b2,
                                               const float* __restrict__ temp) {
    extern __shared__ char sm[];
    uint32_t su = smem_u32(sm);
    int tid = threadIdx.x, lane = tid & 31, wid = tid >> 5;
    int rowbase = blockIdx.x * 128;

    // ================= phase 1: mid = relu(x@W1+b1), hi/lo in smem =========
    int warp_m = wid & 1, warp_n = wid >> 1;      // 2 x 4 warps, 64x64 tiles
    float acc[4][8][4] = {};

    auto load1 = [&](int c, uint32_t bufu) {
        // x fp32: 128 rows x 32 cols = 1024 16B granules (8-granule swizzle)
        #pragma unroll
        for (int g0 = 0; g0 < 1024; g0 += 256) {
            int g = g0 + tid;
            int r = g >> 3, gc = g & 7;
            int rs = rowbase + r; if (rs >= N_NODES) rs = N_NODES - 1;
            const void* src = x + (size_t)rs * NFEAT + c * 32 + gc * 4;
            CP_ASYNC16(bufu + r * 128 + ((gc ^ (r & 7)) << 4), src);
        }
        // B1h + B1l: 256 rows x 32 cols bf16 = 1024 granules each (4-gran swz)
        #pragma unroll
        for (int g0 = 0; g0 < 1024; g0 += 256) {
            int g = g0 + tid;
            int n = g >> 2, gc = g & 3;
            uint32_t d = n * 64 + ((gc ^ (n & 3)) << 4);
            const void* sh = g_B1 + (size_t)n * 1024 + c * 32 + gc * 8;
            CP_ASYNC16(bufu + 16384 + d, sh);
            const void* sl = g_B1 + (size_t)n * 1024 + 512 + c * 32 + gc * 8;
            CP_ASYNC16(bufu + 32768 + d, sl);
        }
    };

    auto convert1 = [&](int bufoff) {
        int row = tid >> 1, half = tid & 1;
        const char* xs = sm + bufoff;
        float4 f[4];
        #pragma unroll
        for (int g = 0; g < 4; g++) {
            int ig = half * 4 + g;
            f[g] = *(const float4*)(xs + row * 128 + ((ig ^ (row & 7)) << 4));
        }
        #pragma unroll
        for (int j = 0; j < 2; j++) {
            float vv[8] = { f[2*j].x, f[2*j].y, f[2*j].z, f[2*j].w,
                            f[2*j+1].x, f[2*j+1].y, f[2*j+1].z, f[2*j+1].w };
            uint32_t hp[4], lp[4];
            #pragma unroll
            for (int q = 0; q < 4; q++) {
                __nv_bfloat162 hh = __floats2bfloat162_rn(vv[2*q], vv[2*q+1]);
                __nv_bfloat162 ll = __floats2bfloat162_rn(vv[2*q]   - __bfloat162float(hh.x),
                                                          vv[2*q+1] - __bfloat162float(hh.y));
                hp[q] = *(uint32_t*)&hh;
                lp[q] = *(uint32_t*)&ll;
            }
            int og = half * 2 + j;
            int phys = og ^ (row & 3);
            *(uint4*)(sm + XH_OFF + row * 64 + phys * 16) = make_uint4(hp[0], hp[1], hp[2], hp[3]);
            *(uint4*)(sm + XL_OFF + row * 64 + phys * 16) = make_uint4(lp[0], lp[1], lp[2], lp[3]);
        }
    };

    auto compute1 = [&](uint32_t bufu) {
        uint32_t Bh = bufu + 16384, Bl = bufu + 32768;
        uint32_t XHu = su + XH_OFF, XLu = su + XL_OFF;
        #pragma unroll
        for (int kk = 0; kk < 2; kk++) {
            uint32_t aH[4][4], aL[4][4], bH[8][2], bL[8][2];
            int kbA = kk * 32 + ((lane >> 4) << 4);
            #pragma unroll
            for (int mi = 0; mi < 4; mi++) {
                int row = warp_m * 64 + mi * 16 + (lane & 15);
                uint32_t ad = XHu + row * 64 + ((((kbA >> 4) ^ (row & 3)) << 4) | (kbA & 15));
                LDSM_X4(aH[mi][0], aH[mi][1], aH[mi][2], aH[mi][3], ad);
            }
            int kbB = kk * 32 + ((lane & 8) ? 16 : 0);
            #pragma unroll
            for (int nj = 0; nj < 4; nj++) {
                int n = warp_n * 64 + nj * 16 + (lane & 7) + ((lane & 16) ? 8 : 0);
                uint32_t off = n * 64 + ((((kbB >> 4) ^ (n & 3)) << 4) | (kbB & 15));
                uint32_t r0, r1, r2, r3;
                LDSM_X4(r0, r1, r2, r3, Bh + off);
                bH[nj * 2][0] = r0;     bH[nj * 2][1] = r1;
                bH[nj * 2 + 1][0] = r2; bH[nj * 2 + 1][1] = r3;
            }
            #pragma unroll
            for (int mi = 0; mi < 4; mi++)
                #pragma unroll
                for (int ni = 0; ni < 8; ni++)
                    MMA16816(acc[mi][ni], aH[mi], bH[ni]);
            #pragma unroll
            for (int nj = 0; nj < 4; nj++) {
                int n = warp_n * 64 + nj * 16 + (lane & 7) + ((lane & 16) ? 8 : 0);
                uint32_t off = n * 64 + ((((kbB >> 4) ^ (n & 3)) << 4) | (kbB & 15));
                uint32_t r0, r1, r2, r3;
                LDSM_X4(r0, r1, r2, r3, Bl + off);
                bL[nj * 2][0] = r0;     bL[nj * 2][1] = r1;
                bL[nj * 2 + 1][0] = r2; bL[nj * 2 + 1][1] = r3;
            }
            #pragma unroll
            for (int mi = 0; mi < 4; mi++)
                #pragma unroll
                for (int ni = 0; ni < 8; ni++)
                    MMA16816(acc[mi][ni], aH[mi], bL[ni]);
            #pragma unroll
            for (int mi = 0; mi < 4; mi++) {
                int row = warp_m * 64 + mi * 16 + (lane & 15);
                uint32_t ad = XLu + row * 64 + ((((kbA >> 4) ^ (row & 3)) << 4) | (kbA & 15));
                LDSM_X4(aL[mi][0], aL[mi][1], aL[mi][2], aL[mi][3], ad);
            }
            #pragma unroll
            for (int mi = 0; mi < 4; mi++)
                #pragma unroll
                for (int ni = 0; ni < 8; ni++)
                    MMA16816(acc[mi][ni], aL[mi], bH[ni]);
        }
    };

    load1(0, su);
    CP_COMMIT();
    for (int c = 0; c < 16; c++) {
        uint32_t buf = su + (c & 1) * ST1;
        if (c + 1 < 16) {
            load1(c + 1, su + ((c + 1) & 1) * ST1);
            CP_COMMIT();
            CP_WAIT1();
        } else {
            CP_WAIT0();
        }
        __syncthreads();
        convert1((c & 1) * ST1);
        __syncthreads();
        compute1(buf);
        __syncthreads();
    }

    // epilogue 1: bias + relu + hi/lo split -> mid smem tiles (4 x 128x64 blk)
    #pragma unroll
    for (int mi = 0; mi < 4; mi++) {
        #pragma unroll
        for (int h = 0; h < 2; h++) {
            int r = warp_m * 64 + mi * 16 + (lane >> 2) + h * 8;
            #pragma unroll
            for (int ni = 0; ni < 8; ni++) {
                int cg = warp_n * 64 + ni * 8 + (lane & 3) * 2;
                float v0 = acc[mi][ni][2 * h]     + __ldg(&b1[cg]);
                float v1 = acc[mi][ni][2 * h + 1] + __ldg(&b1[cg + 1]);
                v0 = fmaxf(v0, 0.f);
                v1 = fmaxf(v1, 0.f);
                __nv_bfloat162 hh = __floats2bfloat162_rn(v0, v1);
                __nv_bfloat162 ll = __floats2bfloat162_rn(v0 - __bfloat162float(hh.x),
                                                          v1 - __bfloat162float(hh.y));
                int blk = cg >> 6, kb = (cg & 63) * 2;
                uint32_t off = blk * 16384 + r * 128 + ((((kb >> 4) ^ (r & 7)) << 4) | (kb & 15));
                *(uint32_t*)(sm + MIDH_OFF + off) = *(uint32_t*)&hh;
                *(uint32_t*)(sm + MIDL_OFF + off) = *(uint32_t*)&ll;
            }
        }
    }
    __syncthreads();

    // ================= phase 2: h0 = mid@W2 + b2 ; hidden = temp[0]*h0 =====
    int warp_m2 = wid >> 1, warp_n2 = wid & 1;    // 4 x 2 warps, 32x32 tiles
    float acc2[2][4][4] = {};

    auto loadB2 = [&](int s, uint32_t bufu) {
        int kc = (s < 8) ? s : (s - 8);
        #pragma unroll
        for (int g0 = 0; g0 < 512; g0 += 256) {
            int g = g0 + tid;
            int n = g >> 3, gc = g & 7;
            const void* src = g_B2 + (size_t)n * 512 + kc * 64 + gc * 8;
            CP_ASYNC16(bufu + n * 128 + ((gc ^ (n & 7)) << 4), src);
        }
    };

    auto compute2 = [&](int s, uint32_t bufu) {
        uint32_t Au = su + ((s < 8) ? MIDH_OFF : MIDL_OFF) + (s & 3) * 16384;
        #pragma unroll
        for (int kk = 0; kk < 4; kk++) {
            uint32_t a[2][4], b[4][2];
            int kbA = kk * 32 + ((lane >> 4) << 4);
            #pragma unroll
            for (int mi = 0; mi < 2; mi++) {
                int row = warp_m2 * 32 + mi * 16 + (lane & 15);
                uint32_t ad = Au + row * 128 + ((((kbA >> 4) ^ (row & 7)) << 4) | (kbA & 15));
                LDSM_X4(a[mi][0], a[mi][1], a[mi][2], a[mi][3], ad);
            }
            int kbB = kk * 32 + ((lane & 8) ? 16 : 0);
            #pragma unroll
            for (int nj = 0; nj < 2; nj++) {
                int n = warp_n2 * 32 + nj * 16 + (lane & 7) + ((lane & 16) ? 8 : 0);
                uint32_t off = n * 128 + ((((kbB >> 4) ^ (n & 7)) << 4) | (kbB & 15));
                uint32_t r0, r1, r2, r3;
                LDSM_X4(r0, r1, r2, r3, bufu + off);
                b[nj * 2][0] = r0;     b[nj * 2][1] = r1;
                b[nj * 2 + 1][0] = r2; b[nj * 2 + 1][1] = r3;
            }
            #pragma unroll
            for (int mi = 0; mi < 2; mi++)
                #pragma unroll
                for (int ni = 0; ni < 4; ni++)
                    MMA16816(acc2[mi][ni], a[mi], b[ni]);
        }
    };

    loadB2(0, su + B2_OFF);
    CP_COMMIT();
    for (int s = 0; s < 12; s++) {
        if (s + 1 < 12) {
            loadB2(s + 1, su + B2_OFF + ((s + 1) & 1) * 8192);
            CP_COMMIT();
            CP_WAIT1();
        } else {
            CP_WAIT0();
        }
        __syncthreads();
        compute2(s, su + B2_OFF + (s & 1) * 8192);
        __syncthreads();
    }

    float t0 = __ldg(&temp[0]);
    #pragma unroll
    for (int mi = 0; mi < 2; mi++) {
        #pragma unroll
        for (int h = 0; h < 2; h++) {
            int r = rowbase + warp_m2 * 32 + mi * 16 + (lane >> 2) + h * 8;
            if (r < N_NODES) {
                #pragma unroll
                for (int ni = 0; ni < 4; ni++) {
                    int col = warp_n2 * 32 + ni * 8 + (lane & 3) * 2;
                    float v0 = acc2[mi][ni][2 * h]     + __ldg(&b2[col]);
                    float v1 = acc2[mi][ni][2 * h + 1] + __ldg(&b2[col + 1]);
                    *(__half2*)&g_h0[(size_t)r * NCLASS + col] = __floats2half2_rn(v0, v1);
                    *(float2*)&g_hidden[(size_t)r * NCLASS + col] = make_float2(t0 * v0, t0 * v1);
                }
            }
        }
    }
}

// ---------------- propagation: fp16 gather; last iter fuses log_softmax -----
__global__ __launch_bounds__(256) void k_prop(int parity,
                                              const float* __restrict__ temp,
                                              int kidx, int last,
                                              float* __restrict__ out) {
    int t = blockIdx.x * blockDim.x + threadIdx.x;
    int c = t >> 5, lane = t & 31;
    if (c >= N_NODES) return;
    const __half2* hin2 = (const __half2*)(parity ? g_h1 : g_h0);
    __half2*       hout2 = (__half2*)(parity ? g_h0 : g_h1);

    float dc = g_dinv[c];
    float sw = dc * dc;
    float2 v = __half22float2(hin2[(size_t)c * 32 + lane]);
    float2 acc;
    acc.x = sw * v.x;
    acc.y = sw * v.y;

    int b = g_off[c], e = g_off[c + 1];
    for (int p = b; p < e; p++) {
        float2 ed = __ldg(&g_edge[p]);
        int s = __float_as_int(ed.x);
        float w = ed.y;
        float2 hv = __half22float2(hin2[(size_t)s * 32 + lane]);
        acc.x = fmaf(w, hv.x, acc.x);
        acc.y = fmaf(w, hv.y, acc.y);
    }

    float tk = temp[kidx];
    float2* hid2 = (float2*)g_hidden;
    float2 h = hid2[(size_t)c * 32 + lane];
    h.x = fmaf(tk, acc.x, h.x);
    h.y = fmaf(tk, acc.y, h.y);

    if (!last) {
        hout2[(size_t)c * 32 + lane] = __floats2half2_rn(acc.x, acc.y);
        hid2[(size_t)c * 32 + lane] = h;
    } else {
        float m = fmaxf(h.x, h.y);
        #pragma unroll
        for (int o = 16; o > 0; o >>= 1) m = fmaxf(m, __shfl_xor_sync(0xFFFFFFFFu, m, o));
        float s = expf(h.x - m) + expf(h.y - m);
        #pragma unroll
        for (int o = 16; o > 0; o >>= 1) s += __shfl_xor_sync(0xFFFFFFFFu, s, o);
        float ls = m + logf(s);
        ((float2*)out)[(size_t)c * 32 + lane] = make_float2(h.x - ls, h.y - ls);
    }
}

// ---------------- driver ----------------
extern "C" void kernel_launch(void* const* d_in, const int* in_sizes, int n_in,
                              void* d_out, int out_size) {
    const float* x    = (const float*)d_in[0];
    const void*  ei   = d_in[1];
    const float* W1   = (const float*)d_in[2];
    const float* b1   = (const float*)d_in[3];
    const float* W2   = (const float*)d_in[4];
    const float* b2   = (const float*)d_in[5];
    const float* temp = (const float*)d_in[6];
    float* out = (float*)d_out;

    cudaFuncSetAttribute(k_fused, cudaFuncAttributeMaxDynamicSharedMemorySize, SMEMF);

    k_detect<<<1, 32>>>((const int*)ei);
    k_init<<<(N_NODES + 255) / 256, 256>>>();
    k_convert<<<(N_EDGES + 255) / 256, 256>>>(ei);
    k_dinv<<<(N_NODES + 255) / 256, 256>>>();
    k_scan<<<1, 1024>>>();
    k_scatter<<<(N_EDGES + 255) / 256, 256>>>();

    k_split_w1<<<(HIDDEN * 1024 + 255) / 256, 256>>>(W1);
    k_split_w2<<<(NCLASS * 512 + 255) / 256, 256>>>(W2);

    k_fused<<<M_PAD / 128, 256, SMEMF>>>(x, b1, b2, temp);

    const int prop_blocks = (N_NODES * 32 + 255) / 256;
    for (int k = 0; k < KITER; k++)
        k_prop<<<prop_blocks, 256>>>(k & 1, temp, k + 1, (k == KITER - 1) ? 1 : 0, out);
}

// round 13
// speedup vs baseline: 1.6967x; 1.0901x over previous
#include <cuda_runtime.h>
#include <cuda_bf16.h>
#include <cuda_fp16.h>
#include <math.h>
#include <stdint.h>

#define N_NODES 100000
#define N_EDGES 3200000
#define NFEAT   512
#define HIDDEN  256
#define NCLASS  64
#define KITER   10
#define M_PAD   100096   // 782 * 128
#define NB      ((N_NODES + 255) / 256)   // 391
#define HSZ     ((size_t)N_NODES * NCLASS)

// ---------------- device scratch (no allocations allowed) ----------------
__device__ int    g_is64;
__device__ int    g_ecnt[N_NODES];
__device__ int    g_pos[N_NODES];
__device__ int    g_off[N_NODES + 1];
__device__ int    g_bsum[NB];
__device__ int    g_boff[NB];
__device__ float  g_dinv[N_NODES];
__device__ float2 g_edge[N_EDGES];
__device__ __align__(256) __nv_bfloat16 g_B1[(size_t)HIDDEN * 1024];  // [256][1024]: W1h|W1l
__device__ __align__(256) __nv_bfloat16 g_B2[(size_t)NCLASS * 512];   // [64][512]:  W2h|W2l
__device__ __align__(256) __half g_hk[(size_t)(KITER + 1) * HSZ];     // fp16 prop states h_0..h_10

// ---------------- PTX helpers (baseline PTX only: sm_80-era) ----------------
__device__ __forceinline__ uint32_t smem_u32(const void* p) {
    uint32_t a;
    asm("{ .reg .u64 t; cvta.to.shared.u64 t, %1; cvt.u32.u64 %0, t; }" : "=r"(a) : "l"(p));
    return a;
}
#define CP_ASYNC16(dst, src) \
    asm volatile("cp.async.cg.shared.global [%0], [%1], 16;" :: "r"(dst), "l"(src) : "memory")
#define CP_COMMIT() asm volatile("cp.async.commit_group;" ::: "memory")
#define CP_WAIT1()  asm volatile("cp.async.wait_group 1;" ::: "memory")
#define CP_WAIT0()  asm volatile("cp.async.wait_group 0;" ::: "memory")

#define LDSM_X4(r0, r1, r2, r3, addr)                                         \
    asm volatile("ldmatrix.sync.aligned.m8n8.x4.shared.b16 {%0,%1,%2,%3},[%4];" \
        : "=r"(r0), "=r"(r1), "=r"(r2), "=r"(r3) : "r"(addr))

#define MMA16816(d, a, b)                                                     \
    asm volatile("mma.sync.aligned.m16n8k16.row.col.f32.bf16.bf16.f32 "       \
        "{%0,%1,%2,%3},{%4,%5,%6,%7},{%8,%9},{%0,%1,%2,%3};"                  \
        : "+f"((d)[0]), "+f"((d)[1]), "+f"((d)[2]), "+f"((d)[3])              \
        : "r"((a)[0]), "r"((a)[1]), "r"((a)[2]), "r"((a)[3]),                 \
          "r"((b)[0]), "r"((b)[1]))

// smem layout for fused kernel
#define ST1      49152
#define XH_OFF   98304
#define XL_OFF   106496
#define MIDH_OFF 0
#define MIDL_OFF 65536
#define B2_OFF   131072
#define SMEMF    147456

// ---------------- dtype detection ----------------
__global__ void k_detect(const int* __restrict__ ei32) {
    if (threadIdx.x == 0 && blockIdx.x == 0) {
        int allzero = 1;
        for (int i = 0; i < 64; i++)
            if (ei32[2 * i + 1] != 0) { allzero = 0; break; }
        g_is64 = allzero;
    }
}

// ---------------- graph preprocessing ----------------
__global__ void k_init() {
    int i = blockIdx.x * blockDim.x + threadIdx.x;
    if (i < N_NODES) g_ecnt[i] = 0;
}

// count in-degree: only needs the col (target) half of edge_index
__global__ void k_count(const void* __restrict__ ei) {
    int e = blockIdx.x * blockDim.x + threadIdx.x;
    if (e >= N_EDGES) return;
    int c;
    if (g_is64) c = (int)((const long long*)ei)[(size_t)N_EDGES + e];
    else        c = ((const int*)ei)[(size_t)N_EDGES + e];
    if ((unsigned)c < N_NODES) atomicAdd(&g_ecnt[c], 1);
}

// per-256-block sums of g_ecnt
__global__ void k_bsum() {
    __shared__ int ws[8];
    int b = blockIdx.x, t = threadIdx.x;
    int i = b * 256 + t;
    int v = (i < N_NODES) ? g_ecnt[i] : 0;
    #pragma unroll
    for (int o = 16; o > 0; o >>= 1) v += __shfl_xor_sync(0xFFFFFFFFu, v, o);
    if ((t & 31) == 0) ws[t >> 5] = v;
    __syncthreads();
    if (t == 0) {
        int s = 0;
        #pragma unroll
        for (int j = 0; j < 8; j++) s += ws[j];
        g_bsum[b] = s;
    }
}

// exclusive scan of the 391 block sums (one block)
__global__ void k_scanb() {
    __shared__ int wsum[16];
    int t = threadIdx.x, lane = t & 31, w = t >> 5;
    int v = (t < NB) ? g_bsum[t] : 0;
    int x = v;
    #pragma unroll
    for (int o = 1; o < 32; o <<= 1) {
        int u = __shfl_up_sync(0xFFFFFFFFu, x, o);
        if (lane >= o) x += u;
    }
    if (lane == 31) wsum[w] = x;
    __syncthreads();
    if (t == 0) {
        int run = 0;
        #pragma unroll
        for (int j = 0; j < 16; j++) { int tmp = wsum[j]; wsum[j] = run; run += tmp; }
    }
    __syncthreads();
    if (t < NB) g_boff[t] = wsum[w] + x - v;
}

// final offsets + dinv + pos=0 (fused)
__global__ void k_offsets() {
    __shared__ int wsum[8];
    int b = blockIdx.x, t = threadIdx.x, lane = t & 31, w = t >> 5;
    int i = b * 256 + t;
    int v = (i < N_NODES) ? g_ecnt[i] : 0;
    int x = v;
    #pragma unroll
    for (int o = 1; o < 32; o <<= 1) {
        int u = __shfl_up_sync(0xFFFFFFFFu, x, o);
        if (lane >= o) x += u;
    }
    if (lane == 31) wsum[w] = x;
    __syncthreads();
    if (t == 0) {
        int run = 0;
        #pragma unroll
        for (int j = 0; j < 8; j++) { int tmp = wsum[j]; wsum[j] = run; run += tmp; }
    }
    __syncthreads();
    int off = g_boff[b] + wsum[w] + x - v;
    if (i < N_NODES) {
        g_off[i] = off;
        g_pos[i] = 0;
        g_dinv[i] = rsqrtf((float)(v + 1));
        if (i == N_NODES - 1) g_off[N_NODES] = off + v;
    }
}

__global__ void k_scatter(const void* __restrict__ ei) {
    int e = blockIdx.x * blockDim.x + threadIdx.x;
    if (e >= N_EDGES) return;
    int r, c;
    if (g_is64) {
        const long long* p = (const long long*)ei;
        r = (int)p[e];
        c = (int)p[(size_t)N_EDGES + e];
    } else {
        const int* p = (const int*)ei;
        r = p[e];
        c = p[(size_t)N_EDGES + e];
    }
    if ((unsigned)r >= N_NODES || (unsigned)c >= N_NODES) return;
    int p = g_off[c] + atomicAdd(&g_pos[c], 1);
    if (p >= N_EDGES) return;
    float w = g_dinv[r] * g_dinv[c];
    g_edge[p] = make_float2(__int_as_float(r), w);
}

// ---------------- weight split preprocessing ----------------
__global__ void k_split_w1(const float* __restrict__ W1) {
    int i = blockIdx.x * blockDim.x + threadIdx.x;
    if (i >= HIDDEN * 1024) return;
    int n = i >> 10, k = i & 1023;
    int kk = k & 511;
    bool lo = k >= 512;
    float w = W1[(size_t)kk * HIDDEN + n];
    __nv_bfloat16 h = __float2bfloat16(w);
    g_B1[i] = lo ? __float2bfloat16(w - __bfloat162float(h)) : h;
}

__global__ void k_split_w2(const float* __restrict__ W2) {
    int i = blockIdx.x * blockDim.x + threadIdx.x;
    if (i >= NCLASS * 512) return;
    int n = i >> 9, k = i & 511;
    int kk = k & 255;
    bool lo = k >= 256;
    float w = W2[(size_t)kk * NCLASS + n];
    __nv_bfloat16 h = __float2bfloat16(w);
    g_B2[i] = lo ? __float2bfloat16(w - __bfloat162float(h)) : h;
}

// ---------------- fused MLP: h0 = relu(x@W1+b1)@W2+b2 (fp16 out) ------------
__global__ __launch_bounds__(256) void k_fused(const float* __restrict__ x,
                                               const float* __restrict__ b1,
                                               const float* __restrict__ b2) {
    extern __shared__ char sm[];
    uint32_t su = smem_u32(sm);
    int tid = threadIdx.x, lane = tid & 31, wid = tid >> 5;
    int rowbase = blockIdx.x * 128;

    // ================= phase 1 =================
    int warp_m = wid & 1, warp_n = wid >> 1;
    float acc[4][8][4] = {};

    auto load1 = [&](int c, uint32_t bufu) {
        #pragma unroll
        for (int g0 = 0; g0 < 1024; g0 += 256) {
            int g = g0 + tid;
            int r = g >> 3, gc = g & 7;
            int rs = rowbase + r; if (rs >= N_NODES) rs = N_NODES - 1;
            const void* src = x + (size_t)rs * NFEAT + c * 32 + gc * 4;
            CP_ASYNC16(bufu + r * 128 + ((gc ^ (r & 7)) << 4), src);
        }
        #pragma unroll
        for (int g0 = 0; g0 < 1024; g0 += 256) {
            int g = g0 + tid;
            int n = g >> 2, gc = g & 3;
            uint32_t d = n * 64 + ((gc ^ (n & 3)) << 4);
            const void* sh = g_B1 + (size_t)n * 1024 + c * 32 + gc * 8;
            CP_ASYNC16(bufu + 16384 + d, sh);
            const void* sl = g_B1 + (size_t)n * 1024 + 512 + c * 32 + gc * 8;
            CP_ASYNC16(bufu + 32768 + d, sl);
        }
    };

    auto convert1 = [&](int bufoff) {
        int row = tid >> 1, half = tid & 1;
        const char* xs = sm + bufoff;
        float4 f[4];
        #pragma unroll
        for (int g = 0; g < 4; g++) {
            int ig = half * 4 + g;
            f[g] = *(const float4*)(xs + row * 128 + ((ig ^ (row & 7)) << 4));
        }
        #pragma unroll
        for (int j = 0; j < 2; j++) {
            float vv[8] = { f[2*j].x, f[2*j].y, f[2*j].z, f[2*j].w,
                            f[2*j+1].x, f[2*j+1].y, f[2*j+1].z, f[2*j+1].w };
            uint32_t hp[4], lp[4];
            #pragma unroll
            for (int q = 0; q < 4; q++) {
                __nv_bfloat162 hh = __floats2bfloat162_rn(vv[2*q], vv[2*q+1]);
                __nv_bfloat162 ll = __floats2bfloat162_rn(vv[2*q]   - __bfloat162float(hh.x),
                                                          vv[2*q+1] - __bfloat162float(hh.y));
                hp[q] = *(uint32_t*)&hh;
                lp[q] = *(uint32_t*)&ll;
            }
            int og = half * 2 + j;
            int phys = og ^ (row & 3);
            *(uint4*)(sm + XH_OFF + row * 64 + phys * 16) = make_uint4(hp[0], hp[1], hp[2], hp[3]);
            *(uint4*)(sm + XL_OFF + row * 64 + phys * 16) = make_uint4(lp[0], lp[1], lp[2], lp[3]);
        }
    };

    auto compute1 = [&](uint32_t bufu) {
        uint32_t Bh = bufu + 16384, Bl = bufu + 32768;
        uint32_t XHu = su + XH_OFF, XLu = su + XL_OFF;
        #pragma unroll
        for (int kk = 0; kk < 2; kk++) {
            uint32_t aH[4][4], aL[4][4], bH[8][2], bL[8][2];
            int kbA = kk * 32 + ((lane >> 4) << 4);
            #pragma unroll
            for (int mi = 0; mi < 4; mi++) {
                int row = warp_m * 64 + mi * 16 + (lane & 15);
                uint32_t ad = XHu + row * 64 + ((((kbA >> 4) ^ (row & 3)) << 4) | (kbA & 15));
                LDSM_X4(aH[mi][0], aH[mi][1], aH[mi][2], aH[mi][3], ad);
            }
            int kbB = kk * 32 + ((lane & 8) ? 16 : 0);
            #pragma unroll
            for (int nj = 0; nj < 4; nj++) {
                int n = warp_n * 64 + nj * 16 + (lane & 7) + ((lane & 16) ? 8 : 0);
                uint32_t off = n * 64 + ((((kbB >> 4) ^ (n & 3)) << 4) | (kbB & 15));
                uint32_t r0, r1, r2, r3;
                LDSM_X4(r0, r1, r2, r3, Bh + off);
                bH[nj * 2][0] = r0;     bH[nj * 2][1] = r1;
                bH[nj * 2 + 1][0] = r2; bH[nj * 2 + 1][1] = r3;
            }
            #pragma unroll
            for (int mi = 0; mi < 4; mi++)
                #pragma unroll
                for (int ni = 0; ni < 8; ni++)
                    MMA16816(acc[mi][ni], aH[mi], bH[ni]);
            #pragma unroll
            for (int nj = 0; nj < 4; nj++) {
                int n = warp_n * 64 + nj * 16 + (lane & 7) + ((lane & 16) ? 8 : 0);
                uint32_t off = n * 64 + ((((kbB >> 4) ^ (n & 3)) << 4) | (kbB & 15));
                uint32_t r0, r1, r2, r3;
                LDSM_X4(r0, r1, r2, r3, Bl + off);
                bL[nj * 2][0] = r0;     bL[nj * 2][1] = r1;
                bL[nj * 2 + 1][0] = r2; bL[nj * 2 + 1][1] = r3;
            }
            #pragma unroll
            for (int mi = 0; mi < 4; mi++)
                #pragma unroll
                for (int ni = 0; ni < 8; ni++)
                    MMA16816(acc[mi][ni], aH[mi], bL[ni]);
            #pragma unroll
            for (int mi = 0; mi < 4; mi++) {
                int row = warp_m * 64 + mi * 16 + (lane & 15);
                uint32_t ad = XLu + row * 64 + ((((kbA >> 4) ^ (row & 3)) << 4) | (kbA & 15));
                LDSM_X4(aL[mi][0], aL[mi][1], aL[mi][2], aL[mi][3], ad);
            }
            #pragma unroll
            for (int mi = 0; mi < 4; mi++)
                #pragma unroll
                for (int ni = 0; ni < 8; ni++)
                    MMA16816(acc[mi][ni], aL[mi], bH[ni]);
        }
    };

    load1(0, su);
    CP_COMMIT();
    for (int c = 0; c < 16; c++) {
        uint32_t buf = su + (c & 1) * ST1;
        if (c + 1 < 16) {
            load1(c + 1, su + ((c + 1) & 1) * ST1);
            CP_COMMIT();
            CP_WAIT1();
        } else {
            CP_WAIT0();
        }
        __syncthreads();
        convert1((c & 1) * ST1);
        __syncthreads();
        compute1(buf);
        __syncthreads();
    }

    #pragma unroll
    for (int mi = 0; mi < 4; mi++) {
        #pragma unroll
        for (int h = 0; h < 2; h++) {
            int r = warp_m * 64 + mi * 16 + (lane >> 2) + h * 8;
            #pragma unroll
            for (int ni = 0; ni < 8; ni++) {
                int cg = warp_n * 64 + ni * 8 + (lane & 3) * 2;
                float v0 = acc[mi][ni][2 * h]     + __ldg(&b1[cg]);
                float v1 = acc[mi][ni][2 * h + 1] + __ldg(&b1[cg + 1]);
                v0 = fmaxf(v0, 0.f);
                v1 = fmaxf(v1, 0.f);
                __nv_bfloat162 hh = __floats2bfloat162_rn(v0, v1);
                __nv_bfloat162 ll = __floats2bfloat162_rn(v0 - __bfloat162float(hh.x),
                                                          v1 - __bfloat162float(hh.y));
                int blk = cg >> 6, kb = (cg & 63) * 2;
                uint32_t off = blk * 16384 + r * 128 + ((((kb >> 4) ^ (r & 7)) << 4) | (kb & 15));
                *(uint32_t*)(sm + MIDH_OFF + off) = *(uint32_t*)&hh;
                *(uint32_t*)(sm + MIDL_OFF + off) = *(uint32_t*)&ll;
            }
        }
    }
    __syncthreads();

    // ================= phase 2 =================
    int warp_m2 = wid >> 1, warp_n2 = wid & 1;
    float acc2[2][4][4] = {};

    auto loadB2 = [&](int s, uint32_t bufu) {
        int kc = (s < 8) ? s : (s - 8);
        #pragma unroll
        for (int g0 = 0; g0 < 512; g0 += 256) {
            int g = g0 + tid;
            int n = g >> 3, gc = g & 7;
            const void* src = g_B2 + (size_t)n * 512 + kc * 64 + gc * 8;
            CP_ASYNC16(bufu + n * 128 + ((gc ^ (n & 7)) << 4), src);
        }
    };

    auto compute2 = [&](int s, uint32_t bufu) {
        uint32_t Au = su + ((s < 8) ? MIDH_OFF : MIDL_OFF) + (s & 3) * 16384;
        #pragma unroll
        for (int kk = 0; kk < 4; kk++) {
            uint32_t a[2][4], b[4][2];
            int kbA = kk * 32 + ((lane >> 4) << 4);
            #pragma unroll
            for (int mi = 0; mi < 2; mi++) {
                int row = warp_m2 * 32 + mi * 16 + (lane & 15);
                uint32_t ad = Au + row * 128 + ((((kbA >> 4) ^ (row & 7)) << 4) | (kbA & 15));
                LDSM_X4(a[mi][0], a[mi][1], a[mi][2], a[mi][3], ad);
            }
            int kbB = kk * 32 + ((lane & 8) ? 16 : 0);
            #pragma unroll
            for (int nj = 0; nj < 2; nj++) {
                int n = warp_n2 * 32 + nj * 16 + (lane & 7) + ((lane & 16) ? 8 : 0);
                uint32_t off = n * 128 + ((((kbB >> 4) ^ (n & 7)) << 4) | (kbB & 15));
                uint32_t r0, r1, r2, r3;
                LDSM_X4(r0, r1, r2, r3, bufu + off);
                b[nj * 2][0] = r0;     b[nj * 2][1] = r1;
                b[nj * 2 + 1][0] = r2; b[nj * 2 + 1][1] = r3;
            }
            #pragma unroll
            for (int mi = 0; mi < 2; mi++)
                #pragma unroll
                for (int ni = 0; ni < 4; ni++)
                    MMA16816(acc2[mi][ni], a[mi], b[ni]);
        }
    };

    loadB2(0, su + B2_OFF);
    CP_COMMIT();
    for (int s = 0; s < 12; s++) {
        if (s + 1 < 12) {
            loadB2(s + 1, su + B2_OFF + ((s + 1) & 1) * 8192);
            CP_COMMIT();
            CP_WAIT1();
        } else {
            CP_WAIT0();
        }
        __syncthreads();
        compute2(s, su + B2_OFF + (s & 1) * 8192);
        __syncthreads();
    }

    #pragma unroll
    for (int mi = 0; mi < 2; mi++) {
        #pragma unroll
        for (int h = 0; h < 2; h++) {
            int r = rowbase + warp_m2 * 32 + mi * 16 + (lane >> 2) + h * 8;
            if (r < N_NODES) {
                #pragma unroll
                for (int ni = 0; ni < 4; ni++) {
                    int col = warp_n2 * 32 + ni * 8 + (lane & 3) * 2;
                    float v0 = acc2[mi][ni][2 * h]     + __ldg(&b2[col]);
                    float v1 = acc2[mi][ni][2 * h + 1] + __ldg(&b2[col + 1]);
                    *(__half2*)&g_hk[(size_t)r * NCLASS + col] = __floats2half2_rn(v0, v1);
                }
            }
        }
    }
}

// ---------------- propagation: h_{k+1} = Ahat @ h_k (fp16 states) -----------
__global__ __launch_bounds__(256) void k_prop(int k) {
    int t = blockIdx.x * blockDim.x + threadIdx.x;
    int c = t >> 5, lane = t & 31;
    if (c >= N_NODES) return;
    const __half2* hin2 = (const __half2*)(g_hk + (size_t)k * HSZ);
    __half2*       hout2 = (__half2*)(g_hk + (size_t)(k + 1) * HSZ);

    float dc = g_dinv[c];
    float sw = dc * dc;
    float2 v = __half22float2(hin2[(size_t)c * 32 + lane]);
    float2 acc;
    acc.x = sw * v.x;
    acc.y = sw * v.y;

    int b = g_off[c], e = g_off[c + 1];
    for (int p = b; p < e; p++) {
        float2 ed = __ldg(&g_edge[p]);
        int s = __float_as_int(ed.x);
        float w = ed.y;
        float2 hv = __half22float2(hin2[(size_t)s * 32 + lane]);
        acc.x = fmaf(w, hv.x, acc.x);
        acc.y = fmaf(w, hv.y, acc.y);
    }
    hout2[(size_t)c * 32 + lane] = __floats2half2_rn(acc.x, acc.y);
}

// ---------------- final: out = log_softmax(sum_k temp[k] * h_k) -------------
__global__ __launch_bounds__(256) void k_final(const float* __restrict__ temp,
                                               float* __restrict__ out) {
    int t = blockIdx.x * blockDim.x + threadIdx.x;
    int c = t >> 5, lane = t & 31;
    if (c >= N_NODES) return;
    size_t idx = (size_t)c * 32 + lane;
    float2 s2 = make_float2(0.f, 0.f);
    #pragma unroll
    for (int k = 0; k <= KITER; k++) {
        float tk = __ldg(&temp[k]);
        float2 v = __half22float2(((const __half2*)(g_hk + (size_t)k * HSZ))[idx]);
        s2.x = fmaf(tk, v.x, s2.x);
        s2.y = fmaf(tk, v.y, s2.y);
    }
    float m = fmaxf(s2.x, s2.y);
    #pragma unroll
    for (int o = 16; o > 0; o >>= 1) m = fmaxf(m, __shfl_xor_sync(0xFFFFFFFFu, m, o));
    float s = expf(s2.x - m) + expf(s2.y - m);
    #pragma unroll
    for (int o = 16; o > 0; o >>= 1) s += __shfl_xor_sync(0xFFFFFFFFu, s, o);
    float ls = m + logf(s);
    ((float2*)out)[idx] = make_float2(s2.x - ls, s2.y - ls);
}

// ---------------- driver ----------------
extern "C" void kernel_launch(void* const* d_in, const int* in_sizes, int n_in,
                              void* d_out, int out_size) {
    const float* x    = (const float*)d_in[0];
    const void*  ei   = d_in[1];
    const float* W1   = (const float*)d_in[2];
    const float* b1   = (const float*)d_in[3];
    const float* W2   = (const float*)d_in[4];
    const float* b2   = (const float*)d_in[5];
    const float* temp = (const float*)d_in[6];
    float* out = (float*)d_out;

    cudaFuncSetAttribute(k_fused, cudaFuncAttributeMaxDynamicSharedMemorySize, SMEMF);

    k_detect<<<1, 32>>>((const int*)ei);
    k_init<<<NB, 256>>>();
    k_count<<<(N_EDGES + 255) / 256, 256>>>(ei);
    k_bsum<<<NB, 256>>>();
    k_scanb<<<1, 512>>>();
    k_offsets<<<NB, 256>>>();
    k_scatter<<<(N_EDGES + 255) / 256, 256>>>(ei);

    k_split_w1<<<(HIDDEN * 1024 + 255) / 256, 256>>>(W1);
    k_split_w2<<<(NCLASS * 512 + 255) / 256, 256>>>(W2);

    k_fused<<<M_PAD / 128, 256, SMEMF>>>(x, b1, b2);

    const int prop_blocks = (N_NODES * 32 + 255) / 256;
    for (int k = 0; k < KITER; k++)
        k_prop<<<prop_blocks, 256>>>(k);

    k_final<<<prop_blocks, 256>>>(temp, out);
}